// round 4
// baseline (speedup 1.0000x reference)
#include <cuda_runtime.h>
#include <cuda_fp16.h>
#include <cstdint>
#include <cstddef>

// ---------------------------------------------------------------------------
// Problem constants (fixed by the dataset)
// ---------------------------------------------------------------------------
#define N_NODES 50000
#define N_EDGES 1600000
#define NFEAT   512
#define NHID    64
#define H1      8
#define NCLASS  16
#define HCAT    (H1 * NHID)   // 512
#define ALPHA   0.2f

// ---------------------------------------------------------------------------
// Scratch (device globals; no allocation allowed)
// ---------------------------------------------------------------------------
__device__ __half g_h1h[(size_t)H1 * N_NODES * NHID];   // layer1 features (fp16)
__device__ float g_hcat[(size_t)N_NODES * HCAT];        // concat(elu(h_prime1))
__device__ float g_h2[(size_t)N_NODES * NCLASS];        // layer2 linear
__device__ float g_p2[(size_t)N_NODES * NCLASS];        // layer2 aggregated
__device__ float g_s1src[H1 * N_NODES];
__device__ float g_s1dst[H1 * N_NODES];
__device__ float g_s2src[N_NODES];
__device__ float g_s2dst[N_NODES];
__device__ int   g_deg[N_NODES];
__device__ int   g_rowptr[N_NODES + 1];
__device__ int   g_fill[N_NODES];
__device__ int   g_dst_sorted[N_EDGES];

// ---------------------------------------------------------------------------
// tf32 helpers
// ---------------------------------------------------------------------------
__device__ __forceinline__ uint32_t f2tf32(float x) {
    uint32_t r;
    asm("cvt.rna.tf32.f32 %0, %1;" : "=r"(r) : "f"(x));
    return r;
}

__device__ __forceinline__ void mma_tf32(float4& d,
                                         const uint32_t a0, const uint32_t a1,
                                         const uint32_t a2, const uint32_t a3,
                                         const uint32_t b0, const uint32_t b1) {
    asm volatile(
        "mma.sync.aligned.m16n8k8.row.col.f32.tf32.tf32.f32 "
        "{%0,%1,%2,%3}, {%4,%5,%6,%7}, {%8,%9}, {%0,%1,%2,%3};"
        : "+f"(d.x), "+f"(d.y), "+f"(d.z), "+f"(d.w)
        : "r"(a0), "r"(a1), "r"(a2), "r"(a3), "r"(b0), "r"(b1));
}

// ---------------------------------------------------------------------------
// CSR construction
// ---------------------------------------------------------------------------
__global__ void k_zero_deg() {
    int i = blockIdx.x * blockDim.x + threadIdx.x;
    if (i < N_NODES) g_deg[i] = 0;
}

__global__ void k_degree(const int* __restrict__ ei) {
    int e = blockIdx.x * blockDim.x + threadIdx.x;
    if (e < N_EDGES) atomicAdd(&g_deg[ei[e]], 1);
}

// Single-block exclusive scan over 50000 degrees -> rowptr, fill
__global__ __launch_bounds__(1024) void k_scan() {
    __shared__ int sums[1024];
    int tid = threadIdx.x;
    constexpr int CH = (N_NODES + 1023) / 1024;  // 49
    int start = tid * CH;
    int end = min(start + CH, N_NODES);
    int s = 0;
    for (int i = start; i < end; ++i) s += g_deg[i];
    sums[tid] = s;
    __syncthreads();
    for (int off = 1; off < 1024; off <<= 1) {
        int t = (tid >= off) ? sums[tid - off] : 0;
        __syncthreads();
        sums[tid] += t;
        __syncthreads();
    }
    int running = sums[tid] - s;  // exclusive prefix of this chunk
    for (int i = start; i < end; ++i) {
        g_rowptr[i] = running;
        g_fill[i]   = running;
        running += g_deg[i];
    }
    if (tid == 1023) g_rowptr[N_NODES] = sums[1023];
}

__global__ void k_scatter(const int* __restrict__ ei) {
    int e = blockIdx.x * blockDim.x + threadIdx.x;
    if (e < N_EDGES) {
        int s = ei[e];
        int d = ei[N_EDGES + e];
        int pos = atomicAdd(&g_fill[s], 1);
        g_dst_sorted[pos] = d;
    }
}

// ---------------------------------------------------------------------------
// Layer-1 GEMM via tf32 tensor-core mma.sync, fp16 output.
// C[h][M, 64] = A[M, 512] @ W1[h][512, 64]
// Block tile 128x64x16, 256 threads = 8 warps in 4(m) x 2(n) grid,
// 32x32 per warp = 2(m) x 4(n) m16n8k8 subtiles.
// ---------------------------------------------------------------------------
#define AS_STRIDE 20
#define BS_STRIDE 72

__global__ __launch_bounds__(256) void k_gemm1(
    const float* __restrict__ A, const float* __restrict__ Wbase,
    __half* __restrict__ Cbase)
{
    constexpr int BM = 128, BK = 16, K = NFEAT, BN = 64;
    __shared__ uint32_t As[BM * AS_STRIDE];   // tf32 bits, [m][k]
    __shared__ uint32_t Bs[BK * BS_STRIDE];   // tf32 bits, [k][n]

    int h = blockIdx.y;
    const float* B = Wbase + (size_t)h * K * BN;
    __half* C = Cbase + (size_t)h * N_NODES * BN;

    int m0 = blockIdx.x * BM;
    int tid = threadIdx.x;
    int warp = tid >> 5;
    int lane = tid & 31;
    int g = lane >> 2;        // groupID 0..7
    int t = lane & 3;         // thread-in-group 0..3
    int wm = warp >> 1;       // 0..3 -> m offset wm*32
    int wn = warp & 1;        // 0..1 -> n offset wn*32

    // Global load assignments
    int aRow = tid >> 1;           // 0..127
    int aCol = (tid & 1) * 8;      // 0 or 8
    int bRow = tid >> 4;           // 0..15
    int bCol = (tid & 15) * 4;     // 0..60
    const bool aValid = (m0 + aRow) < N_NODES;
    const float* Aptr = A + (size_t)(m0 + aRow) * K + aCol;
    const float* Bptr = B + (size_t)bRow * BN + bCol;

    float4 acc[2][4];
#pragma unroll
    for (int mi = 0; mi < 2; ++mi)
#pragma unroll
        for (int nj = 0; nj < 4; ++nj)
            acc[mi][nj] = make_float4(0.f, 0.f, 0.f, 0.f);

    for (int k0 = 0; k0 < K; k0 += BK) {
        float4 a0 = make_float4(0.f, 0.f, 0.f, 0.f), a1 = a0;
        if (aValid) {
            a0 = *(const float4*)(Aptr + k0);
            a1 = *(const float4*)(Aptr + k0 + 4);
        }
        float4 b4 = *(const float4*)(Bptr + (size_t)k0 * BN);
        __syncthreads();
        uint32_t* ar = &As[aRow * AS_STRIDE + aCol];
        ar[0] = f2tf32(a0.x); ar[1] = f2tf32(a0.y);
        ar[2] = f2tf32(a0.z); ar[3] = f2tf32(a0.w);
        ar[4] = f2tf32(a1.x); ar[5] = f2tf32(a1.y);
        ar[6] = f2tf32(a1.z); ar[7] = f2tf32(a1.w);
        uint32_t* br = &Bs[bRow * BS_STRIDE + bCol];
        br[0] = f2tf32(b4.x); br[1] = f2tf32(b4.y);
        br[2] = f2tf32(b4.z); br[3] = f2tf32(b4.w);
        __syncthreads();

#pragma unroll
        for (int kk = 0; kk < BK; kk += 8) {
            uint32_t af[2][4];
#pragma unroll
            for (int mi = 0; mi < 2; ++mi) {
                int r = wm * 32 + mi * 16 + g;
                af[mi][0] = As[r * AS_STRIDE + kk + t];
                af[mi][1] = As[(r + 8) * AS_STRIDE + kk + t];
                af[mi][2] = As[r * AS_STRIDE + kk + t + 4];
                af[mi][3] = As[(r + 8) * AS_STRIDE + kk + t + 4];
            }
            uint32_t bf[4][2];
#pragma unroll
            for (int nj = 0; nj < 4; ++nj) {
                int c = wn * 32 + nj * 8 + g;
                bf[nj][0] = Bs[(kk + t) * BS_STRIDE + c];
                bf[nj][1] = Bs[(kk + t + 4) * BS_STRIDE + c];
            }
#pragma unroll
            for (int mi = 0; mi < 2; ++mi)
#pragma unroll
                for (int nj = 0; nj < 4; ++nj)
                    mma_tf32(acc[mi][nj],
                             af[mi][0], af[mi][1], af[mi][2], af[mi][3],
                             bf[nj][0], bf[nj][1]);
        }
    }

    // Epilogue: (c0,c1) -> [row g][cols 2t,2t+1]; (c2,c3) -> row g+8. fp16 out.
#pragma unroll
    for (int mi = 0; mi < 2; ++mi) {
#pragma unroll
        for (int nj = 0; nj < 4; ++nj) {
            int r = m0 + wm * 32 + mi * 16 + g;
            int c = wn * 32 + nj * 8 + t * 2;
            float4 v = acc[mi][nj];
            if (r < N_NODES)
                *(__half2*)&C[(size_t)r * BN + c] = __floats2half2_rn(v.x, v.y);
            if (r + 8 < N_NODES)
                *(__half2*)&C[(size_t)(r + 8) * BN + c] = __floats2half2_rn(v.z, v.w);
        }
    }
}

// ---------------------------------------------------------------------------
// Generic tiled SGEMM (used for layer 2): C[M,ncols] = A[M,K] @ B[K,ncols]
// ---------------------------------------------------------------------------
__global__ __launch_bounds__(256) void k_sgemm(
    const float* __restrict__ A, const float* __restrict__ Bbase,
    float* __restrict__ Cbase, int M, int K, int ncols,
    long bHeadStride, long cHeadStride)
{
    constexpr int BM = 64, BN = 64, BK = 16;
    __shared__ float As[BK][BM];   // transposed A tile
    __shared__ float Bsh[BK][BN];

    int h = blockIdx.y;
    const float* B = Bbase + (size_t)h * bHeadStride;
    float* C = Cbase + (size_t)h * cHeadStride;

    int m0 = blockIdx.x * BM;
    int tid = threadIdx.x;
    int tx = tid & 15, ty = tid >> 4;

    float acc[4][4] = {};

    int aRow = tid >> 2;          // 0..63
    int aCol = (tid & 3) * 4;     // 0,4,8,12
    int bRow = tid >> 4;          // 0..15
    int bCol = (tid & 15) * 4;    // 0..60

    const bool aValid = (m0 + aRow) < M;
    const bool bValid = bCol < ncols;
    const float* Aptr = A + (size_t)(m0 + aRow) * K + aCol;
    const float* Bptr = B + (size_t)bRow * ncols + bCol;

    for (int k0 = 0; k0 < K; k0 += BK) {
        float4 av = aValid ? *(const float4*)(Aptr + k0) : make_float4(0.f, 0.f, 0.f, 0.f);
        float4 bv = bValid ? *(const float4*)(Bptr + (size_t)k0 * ncols) : make_float4(0.f, 0.f, 0.f, 0.f);
        __syncthreads();
        As[aCol + 0][aRow] = av.x;
        As[aCol + 1][aRow] = av.y;
        As[aCol + 2][aRow] = av.z;
        As[aCol + 3][aRow] = av.w;
        *(float4*)&Bsh[bRow][bCol] = bv;
        __syncthreads();
#pragma unroll
        for (int k = 0; k < BK; ++k) {
            float4 a4 = *(const float4*)&As[k][ty * 4];
            float4 b4 = *(const float4*)&Bsh[k][tx * 4];
            float ar[4] = {a4.x, a4.y, a4.z, a4.w};
            float br[4] = {b4.x, b4.y, b4.z, b4.w};
#pragma unroll
            for (int i = 0; i < 4; ++i)
#pragma unroll
                for (int j = 0; j < 4; ++j)
                    acc[i][j] = fmaf(ar[i], br[j], acc[i][j]);
        }
    }

#pragma unroll
    for (int i = 0; i < 4; ++i) {
        int r = m0 + ty * 4 + i;
        if (r >= M) break;
#pragma unroll
        for (int j = 0; j < 4; ++j) {
            int c = tx * 4 + j;
            if (c < ncols) C[(size_t)r * ncols + c] = acc[i][j];
        }
    }
}

// ---------------------------------------------------------------------------
// Layer-1 attention scores from fp16 h1: warp per (node, head)
// ---------------------------------------------------------------------------
__global__ __launch_bounds__(256) void k_scores1(const float* __restrict__ a1) {
    int warp = threadIdx.x >> 5;
    int lane = threadIdx.x & 31;
    int n = blockIdx.x * 8 + warp;
    int h = blockIdx.y;
    if (n >= N_NODES) return;
    const __half* hp = g_h1h + ((size_t)h * N_NODES + n) * NHID;
    float2 hv = __half22float2(*(const __half2*)(hp + lane * 2));
    const float* a = a1 + h * (2 * NHID);
    float2 as = *(const float2*)(a + lane * 2);
    float2 ad = *(const float2*)(a + NHID + lane * 2);
    float ps = hv.x * as.x + hv.y * as.y;
    float pd = hv.x * ad.x + hv.y * ad.y;
#pragma unroll
    for (int o = 16; o; o >>= 1) {
        ps += __shfl_xor_sync(0xFFFFFFFFu, ps, o);
        pd += __shfl_xor_sync(0xFFFFFFFFu, pd, o);
    }
    if (lane == 0) {
        g_s1src[h * N_NODES + n] = ps;
        g_s1dst[h * N_NODES + n] = pd;
    }
}

// ---------------------------------------------------------------------------
// Layer-1 CSR aggregation, fp16 gather: warp per (node, head); lane = 2 feats.
// Writes elu(agg/rowsum) straight into hcat[n][h*64 + f].
// ---------------------------------------------------------------------------
__global__ __launch_bounds__(256) void k_agg1() {
    int warp = threadIdx.x >> 5;
    int lane = threadIdx.x & 31;
    int n = blockIdx.x * 8 + warp;
    int h = blockIdx.y;
    if (n >= N_NODES) return;
    int beg = g_rowptr[n], end = g_rowptr[n + 1];
    float ssrc = g_s1src[h * N_NODES + n];
    const __half* hb = g_h1h + (size_t)h * N_NODES * NHID;
    const float* sd = g_s1dst + (size_t)h * N_NODES;
    float ax = 0.f, ay = 0.f, rs = 0.f;
    for (int i = beg; i < end; ++i) {
        int v = __ldg(&g_dst_sorted[i]);
        float lg = ssrc + __ldg(&sd[v]);
        lg = lg > 0.f ? lg : ALPHA * lg;
        float e = __expf(-lg);
        rs += e;
        float2 hv = __half22float2(*(const __half2*)(hb + (size_t)v * NHID + lane * 2));
        ax = fmaf(e, hv.x, ax);
        ay = fmaf(e, hv.y, ay);
    }
    float inv = 1.f / rs;
    float o0 = ax * inv, o1 = ay * inv;
    o0 = o0 > 0.f ? o0 : expm1f(o0);
    o1 = o1 > 0.f ? o1 : expm1f(o1);
    *(float2*)(g_hcat + (size_t)n * HCAT + h * NHID + lane * 2) = make_float2(o0, o1);
}

// ---------------------------------------------------------------------------
// Layer-2 scores (16-dim dots, thread per node)
// ---------------------------------------------------------------------------
__global__ void k_scores2(const float* __restrict__ a2) {
    int n = blockIdx.x * blockDim.x + threadIdx.x;
    if (n >= N_NODES) return;
    float ps = 0.f, pd = 0.f;
    const float* hp = g_h2 + (size_t)n * NCLASS;
#pragma unroll
    for (int c = 0; c < NCLASS; ++c) {
        float v = hp[c];
        ps = fmaf(v, __ldg(&a2[c]), ps);
        pd = fmaf(v, __ldg(&a2[NCLASS + c]), pd);
    }
    g_s2src[n] = ps;
    g_s2dst[n] = pd;
}

// ---------------------------------------------------------------------------
// Layer-2 CSR aggregation: thread per (node, class); 2 nodes per warp.
// ---------------------------------------------------------------------------
__global__ __launch_bounds__(256) void k_agg2() {
    int t = blockIdx.x * blockDim.x + threadIdx.x;
    int n = t >> 4;
    int f = t & 15;
    if (n >= N_NODES) return;
    int beg = g_rowptr[n], end = g_rowptr[n + 1];
    float ss = g_s2src[n];
    float acc = 0.f, rs = 0.f;
    for (int i = beg; i < end; ++i) {
        int v = __ldg(&g_dst_sorted[i]);
        float lg = ss + __ldg(&g_s2dst[v]);
        lg = lg > 0.f ? lg : ALPHA * lg;
        float e = __expf(-lg);
        rs += e;
        acc = fmaf(e, __ldg(&g_h2[(size_t)v * NCLASS + f]), acc);
    }
    g_p2[(size_t)n * NCLASS + f] = acc / rs;
}

// ---------------------------------------------------------------------------
// elu + log_softmax over 16 classes, thread per node
// ---------------------------------------------------------------------------
__global__ void k_final(float* __restrict__ out) {
    int n = blockIdx.x * blockDim.x + threadIdx.x;
    if (n >= N_NODES) return;
    float v[NCLASS];
    float m = -1e30f;
#pragma unroll
    for (int c = 0; c < NCLASS; ++c) {
        float x = g_p2[(size_t)n * NCLASS + c];
        x = x > 0.f ? x : expm1f(x);
        v[c] = x;
        m = fmaxf(m, x);
    }
    float s = 0.f;
#pragma unroll
    for (int c = 0; c < NCLASS; ++c) s += __expf(v[c] - m);
    float l = m + logf(s);
#pragma unroll
    for (int c = 0; c < NCLASS; ++c) out[(size_t)n * NCLASS + c] = v[c] - l;
}

// ---------------------------------------------------------------------------
// Launch
// ---------------------------------------------------------------------------
extern "C" void kernel_launch(void* const* d_in, const int* in_sizes, int n_in,
                              void* d_out, int out_size) {
    const float* x  = (const float*)d_in[0];
    const int*   ei = (const int*)d_in[1];
    const float* W1 = (const float*)d_in[2];
    const float* a1 = (const float*)d_in[3];
    const float* W2 = (const float*)d_in[4];
    const float* a2 = (const float*)d_in[5];
    float* out = (float*)d_out;

    void *h1p = nullptr, *hcatp = nullptr, *h2p = nullptr;
    cudaGetSymbolAddress(&h1p, g_h1h);
    cudaGetSymbolAddress(&hcatp, g_hcat);
    cudaGetSymbolAddress(&h2p, g_h2);

    // CSR build
    k_zero_deg<<<(N_NODES + 255) / 256, 256>>>();
    k_degree<<<(N_EDGES + 255) / 256, 256>>>(ei);
    k_scan<<<1, 1024>>>();
    k_scatter<<<(N_EDGES + 255) / 256, 256>>>(ei);

    // Layer 1: tf32 tensor-core GEMM -> fp16 h1
    dim3 g1((N_NODES + 127) / 128, H1);
    k_gemm1<<<g1, 256>>>(x, W1, (__half*)h1p);
    dim3 gw((N_NODES + 7) / 8, H1);
    k_scores1<<<gw, 256>>>(a1);
    k_agg1<<<gw, 256>>>();

    // Layer 2
    dim3 g2((N_NODES + 63) / 64, 1);
    k_sgemm<<<g2, 256>>>((const float*)hcatp, W2, (float*)h2p, N_NODES, HCAT, NCLASS, 0, 0);
    k_scores2<<<(N_NODES + 255) / 256, 256>>>(a2);
    k_agg2<<<(N_NODES * NCLASS + 255) / 256, 256>>>();
    k_final<<<(N_NODES + 255) / 256, 256>>>(out);
}

// round 7
// speedup vs baseline: 1.2797x; 1.2797x over previous
#include <cuda_runtime.h>
#include <cuda_fp16.h>
#include <cstdint>
#include <cstddef>

// ---------------------------------------------------------------------------
// Problem constants (fixed by the dataset)
// ---------------------------------------------------------------------------
#define N_NODES 50000
#define N_EDGES 1600000
#define NFEAT   512
#define NHID    64
#define H1      8
#define NCLASS  16
#define HCAT    (H1 * NHID)   // 512
#define ALPHA   0.2f

// ---------------------------------------------------------------------------
// Scratch (device globals; no allocation allowed)
// ---------------------------------------------------------------------------
__device__ __half g_xh[(size_t)N_NODES * NFEAT];        // x in fp16
__device__ __half g_w1t[(size_t)H1 * NHID * NFEAT];     // W1^T fp16: [h][n][k]
__device__ __half g_w2t[(size_t)NCLASS * HCAT];         // W2^T fp16: [n][k]
__device__ __half g_h1h[(size_t)H1 * N_NODES * NHID];   // layer1 features (fp16)
__device__ __half g_hcath[(size_t)N_NODES * HCAT];      // concat(elu(h')) fp16
__device__ float g_h2[(size_t)N_NODES * NCLASS];        // layer2 linear (fp32)
__device__ float g_p2[(size_t)N_NODES * NCLASS];        // layer2 aggregated
__device__ float g_s1src[H1 * N_NODES];
__device__ float g_s1dst[H1 * N_NODES];
__device__ float g_s2src[N_NODES];
__device__ float g_s2dst[N_NODES];
__device__ int   g_deg[N_NODES];
__device__ int   g_rowptr[N_NODES + 1];
__device__ int   g_fill[N_NODES];
__device__ int   g_dst_sorted[N_EDGES];

// ---------------------------------------------------------------------------
// helpers
// ---------------------------------------------------------------------------
__device__ __forceinline__ uint32_t packh2(float lo, float hi) {
    __half2 h = __floats2half2_rn(lo, hi);
    return *(uint32_t*)&h;
}

__device__ __forceinline__ void mma_fp16(float4& d,
                                         uint32_t a0, uint32_t a1,
                                         uint32_t a2, uint32_t a3,
                                         uint32_t b0, uint32_t b1) {
    asm volatile(
        "mma.sync.aligned.m16n8k16.row.col.f32.f16.f16.f32 "
        "{%0,%1,%2,%3}, {%4,%5,%6,%7}, {%8,%9}, {%0,%1,%2,%3};"
        : "+f"(d.x), "+f"(d.y), "+f"(d.z), "+f"(d.w)
        : "r"(a0), "r"(a1), "r"(a2), "r"(a3), "r"(b0), "r"(b1));
}

// ---------------------------------------------------------------------------
// fp16 conversion kernels
// ---------------------------------------------------------------------------
__global__ void k_cvt_x(const float* __restrict__ x) {
    size_t i = ((size_t)blockIdx.x * blockDim.x + threadIdx.x) * 8;
    if (i >= (size_t)N_NODES * NFEAT) return;
    float4 a = *(const float4*)(x + i);
    float4 b = *(const float4*)(x + i + 4);
    uint4 u;
    u.x = packh2(a.x, a.y); u.y = packh2(a.z, a.w);
    u.z = packh2(b.x, b.y); u.w = packh2(b.z, b.w);
    *(uint4*)&g_xh[i] = u;
}

__global__ void k_cvt_w1(const float* __restrict__ W1) {
    int idx = blockIdx.x * blockDim.x + threadIdx.x;
    if (idx >= H1 * NHID * NFEAT) return;
    int k = idx & (NFEAT - 1);
    int n = (idx >> 9) & (NHID - 1);
    int h = idx >> 15;
    g_w1t[idx] = __float2half(W1[(size_t)h * NFEAT * NHID + (size_t)k * NHID + n]);
}

__global__ void k_cvt_w2(const float* __restrict__ W2) {
    int idx = blockIdx.x * blockDim.x + threadIdx.x;
    if (idx >= NCLASS * HCAT) return;
    int k = idx & (HCAT - 1);
    int n = idx >> 9;
    g_w2t[idx] = __float2half(W2[(size_t)k * NCLASS + n]);
}

// ---------------------------------------------------------------------------
// CSR construction
// ---------------------------------------------------------------------------
__global__ void k_zero_deg() {
    int i = blockIdx.x * blockDim.x + threadIdx.x;
    if (i < N_NODES) g_deg[i] = 0;
}

__global__ void k_degree(const int* __restrict__ ei) {
    int e = blockIdx.x * blockDim.x + threadIdx.x;
    if (e < N_EDGES) atomicAdd(&g_deg[ei[e]], 1);
}

__global__ __launch_bounds__(1024) void k_scan() {
    __shared__ int sums[1024];
    int tid = threadIdx.x;
    constexpr int CH = (N_NODES + 1023) / 1024;  // 49
    int start = tid * CH;
    int end = min(start + CH, N_NODES);
    int s = 0;
    for (int i = start; i < end; ++i) s += g_deg[i];
    sums[tid] = s;
    __syncthreads();
    for (int off = 1; off < 1024; off <<= 1) {
        int t = (tid >= off) ? sums[tid - off] : 0;
        __syncthreads();
        sums[tid] += t;
        __syncthreads();
    }
    int running = sums[tid] - s;
    for (int i = start; i < end; ++i) {
        g_rowptr[i] = running;
        g_fill[i]   = running;
        running += g_deg[i];
    }
    if (tid == 1023) g_rowptr[N_NODES] = sums[1023];
}

__global__ void k_scatter(const int* __restrict__ ei) {
    int e = blockIdx.x * blockDim.x + threadIdx.x;
    if (e < N_EDGES) {
        int s = ei[e];
        int d = ei[N_EDGES + e];
        int pos = atomicAdd(&g_fill[s], 1);
        g_dst_sorted[pos] = d;
    }
}

// ---------------------------------------------------------------------------
// Layer-1 GEMM: fp16 MMA m16n8k16, software-pipelined global loads.
// C[h][M, 64] = xh[M, 512] @ W1t[h][64, 512]^T   (B col-major = [n][k])
// BM=128, BN=64, BK=32, 256 threads = 8 warps (4m x 2n), warp tile 32x32.
// Smem stride 40 halves (20 words) -> conflict-free fragment loads.
// ---------------------------------------------------------------------------
#define G1_STR 40

__global__ __launch_bounds__(256) void k_gemm1(__half* __restrict__ Cbase) {
    constexpr int BM = 128, BN = 64, BK = 32, K = NFEAT;
    __shared__ __half As[BM * G1_STR];
    __shared__ __half Bs[BN * G1_STR];

    int h = blockIdx.y;
    const __half* A = g_xh;
    const __half* B = g_w1t + (size_t)h * NHID * NFEAT;
    __half* C = Cbase + (size_t)h * N_NODES * NHID;

    int m0 = blockIdx.x * BM;
    int tid = threadIdx.x;
    int warp = tid >> 5;
    int lane = tid & 31;
    int g = lane >> 2;
    int t = lane & 3;
    int wm = warp >> 1;       // 0..3
    int wn = warp & 1;        // 0..1

    // global load mapping
    int aRow = tid >> 1;                // 0..127
    int aCol = (tid & 1) * 16;          // 0 or 16
    int bRow = tid >> 2;                // 0..63
    int bCol = (tid & 3) * 8;           // 0,8,16,24
    const bool aValid = (m0 + aRow) < N_NODES;
    const __half* Aptr = A + (size_t)(m0 + aRow) * K + aCol;
    const __half* Bptr = B + (size_t)bRow * K + bCol;

    float4 acc[2][4];
#pragma unroll
    for (int mi = 0; mi < 2; ++mi)
#pragma unroll
        for (int nj = 0; nj < 4; ++nj)
            acc[mi][nj] = make_float4(0.f, 0.f, 0.f, 0.f);

    uint4 ra0, ra1, rb;
    // prologue: k0 = 0
    ra0 = aValid ? *(const uint4*)(Aptr) : make_uint4(0, 0, 0, 0);
    ra1 = aValid ? *(const uint4*)(Aptr + 8) : make_uint4(0, 0, 0, 0);
    rb  = *(const uint4*)(Bptr);

    for (int k0 = 0; k0 < K; k0 += BK) {
        __syncthreads();
        *(uint4*)&As[aRow * G1_STR + aCol]     = ra0;
        *(uint4*)&As[aRow * G1_STR + aCol + 8] = ra1;
        *(uint4*)&Bs[bRow * G1_STR + bCol]     = rb;
        __syncthreads();
        if (k0 + BK < K) {
            ra0 = aValid ? *(const uint4*)(Aptr + k0 + BK) : make_uint4(0, 0, 0, 0);
            ra1 = aValid ? *(const uint4*)(Aptr + k0 + BK + 8) : make_uint4(0, 0, 0, 0);
            rb  = *(const uint4*)(Bptr + k0 + BK);
        }
#pragma unroll
        for (int kk = 0; kk < BK; kk += 16) {
            uint32_t af[2][4];
#pragma unroll
            for (int mi = 0; mi < 2; ++mi) {
                int r = (wm * 32 + mi * 16 + g) * G1_STR + kk + 2 * t;
                af[mi][0] = *(const uint32_t*)&As[r];
                af[mi][1] = *(const uint32_t*)&As[r + 8 * G1_STR];
                af[mi][2] = *(const uint32_t*)&As[r + 8];
                af[mi][3] = *(const uint32_t*)&As[r + 8 * G1_STR + 8];
            }
            uint32_t bf[4][2];
#pragma unroll
            for (int nj = 0; nj < 4; ++nj) {
                int r = (wn * 32 + nj * 8 + g) * G1_STR + kk + 2 * t;
                bf[nj][0] = *(const uint32_t*)&Bs[r];
                bf[nj][1] = *(const uint32_t*)&Bs[r + 8];
            }
#pragma unroll
            for (int mi = 0; mi < 2; ++mi)
#pragma unroll
                for (int nj = 0; nj < 4; ++nj)
                    mma_fp16(acc[mi][nj],
                             af[mi][0], af[mi][1], af[mi][2], af[mi][3],
                             bf[nj][0], bf[nj][1]);
        }
    }

    // Epilogue: (c0,c1) -> [row g][cols 2t,2t+1]; (c2,c3) -> row g+8. fp16 out.
#pragma unroll
    for (int mi = 0; mi < 2; ++mi) {
#pragma unroll
        for (int nj = 0; nj < 4; ++nj) {
            int r = m0 + wm * 32 + mi * 16 + g;
            int c = wn * 32 + nj * 8 + t * 2;
            float4 v = acc[mi][nj];
            if (r < N_NODES) {
                uint32_t p = packh2(v.x, v.y);
                *(uint32_t*)&C[(size_t)r * NHID + c] = p;
            }
            if (r + 8 < N_NODES) {
                uint32_t p = packh2(v.z, v.w);
                *(uint32_t*)&C[(size_t)(r + 8) * NHID + c] = p;
            }
        }
    }
}

// ---------------------------------------------------------------------------
// Layer-2 GEMM: fp16 MMA, BN=16 (no wasted columns).
// h2[M,16] = hcath[M,512] @ W2t[16,512]^T, fp32 out.
// BM=128, BK=32, 256 threads = 8 warps stacked in m (16 rows each).
// ---------------------------------------------------------------------------
__global__ __launch_bounds__(256) void k_gemm2() {
    constexpr int BM = 128, BK = 32, K = HCAT;
    __shared__ __half As[BM * G1_STR];
    __shared__ __half Bs[NCLASS * G1_STR];

    int m0 = blockIdx.x * BM;
    int tid = threadIdx.x;
    int warp = tid >> 5;
    int lane = tid & 31;
    int g = lane >> 2;
    int t = lane & 3;

    int aRow = tid >> 1;
    int aCol = (tid & 1) * 16;
    const bool aValid = (m0 + aRow) < N_NODES;
    const __half* Aptr = g_hcath + (size_t)(m0 + aRow) * K + aCol;
    // B tile: 16 rows x 32 halves = 512 halves -> 64 threads x uint4
    int bRow = tid >> 2;            // 0..63, valid < 16
    int bCol = (tid & 3) * 8;
    const bool bAct = bRow < NCLASS;
    const __half* Bptr = g_w2t + (size_t)bRow * K + bCol;

    float4 acc[2];
    acc[0] = make_float4(0.f, 0.f, 0.f, 0.f);
    acc[1] = make_float4(0.f, 0.f, 0.f, 0.f);

    uint4 ra0, ra1, rb;
    ra0 = aValid ? *(const uint4*)(Aptr) : make_uint4(0, 0, 0, 0);
    ra1 = aValid ? *(const uint4*)(Aptr + 8) : make_uint4(0, 0, 0, 0);
    rb  = bAct ? *(const uint4*)(Bptr) : make_uint4(0, 0, 0, 0);

    for (int k0 = 0; k0 < K; k0 += BK) {
        __syncthreads();
        *(uint4*)&As[aRow * G1_STR + aCol]     = ra0;
        *(uint4*)&As[aRow * G1_STR + aCol + 8] = ra1;
        if (bAct) *(uint4*)&Bs[bRow * G1_STR + bCol] = rb;
        __syncthreads();
        if (k0 + BK < K) {
            ra0 = aValid ? *(const uint4*)(Aptr + k0 + BK) : make_uint4(0, 0, 0, 0);
            ra1 = aValid ? *(const uint4*)(Aptr + k0 + BK + 8) : make_uint4(0, 0, 0, 0);
            rb  = bAct ? *(const uint4*)(Bptr + k0 + BK) : make_uint4(0, 0, 0, 0);
        }
#pragma unroll
        for (int kk = 0; kk < BK; kk += 16) {
            int r = (warp * 16 + g) * G1_STR + kk + 2 * t;
            uint32_t a0 = *(const uint32_t*)&As[r];
            uint32_t a1 = *(const uint32_t*)&As[r + 8 * G1_STR];
            uint32_t a2 = *(const uint32_t*)&As[r + 8];
            uint32_t a3 = *(const uint32_t*)&As[r + 8 * G1_STR + 8];
#pragma unroll
            for (int nj = 0; nj < 2; ++nj) {
                int rb2 = (nj * 8 + g) * G1_STR + kk + 2 * t;
                uint32_t b0 = *(const uint32_t*)&Bs[rb2];
                uint32_t b1 = *(const uint32_t*)&Bs[rb2 + 8];
                mma_fp16(acc[nj], a0, a1, a2, a3, b0, b1);
            }
        }
    }

#pragma unroll
    for (int nj = 0; nj < 2; ++nj) {
        int r = m0 + warp * 16 + g;
        int c = nj * 8 + t * 2;
        float4 v = acc[nj];
        if (r < N_NODES)
            *(float2*)&g_h2[(size_t)r * NCLASS + c] = make_float2(v.x, v.y);
        if (r + 8 < N_NODES)
            *(float2*)&g_h2[(size_t)(r + 8) * NCLASS + c] = make_float2(v.z, v.w);
    }
}

// ---------------------------------------------------------------------------
// Layer-1 attention scores from fp16 h1: warp per (node, head)
// ---------------------------------------------------------------------------
__global__ __launch_bounds__(256) void k_scores1(const float* __restrict__ a1) {
    int warp = threadIdx.x >> 5;
    int lane = threadIdx.x & 31;
    int n = blockIdx.x * 8 + warp;
    int h = blockIdx.y;
    if (n >= N_NODES) return;
    const __half* hp = g_h1h + ((size_t)h * N_NODES + n) * NHID;
    float2 hv = __half22float2(*(const __half2*)(hp + lane * 2));
    const float* a = a1 + h * (2 * NHID);
    float2 as = *(const float2*)(a + lane * 2);
    float2 ad = *(const float2*)(a + NHID + lane * 2);
    float ps = hv.x * as.x + hv.y * as.y;
    float pd = hv.x * ad.x + hv.y * ad.y;
#pragma unroll
    for (int o = 16; o; o >>= 1) {
        ps += __shfl_xor_sync(0xFFFFFFFFu, ps, o);
        pd += __shfl_xor_sync(0xFFFFFFFFu, pd, o);
    }
    if (lane == 0) {
        g_s1src[h * N_NODES + n] = ps;
        g_s1dst[h * N_NODES + n] = pd;
    }
}

// ---------------------------------------------------------------------------
// Layer-1 CSR aggregation, fp16 gather: warp per (node, head); lane = 2 feats.
// Writes elu(agg/rowsum) as fp16 into hcath[n][h*64 + f].
// ---------------------------------------------------------------------------
__global__ __launch_bounds__(256) void k_agg1() {
    int warp = threadIdx.x >> 5;
    int lane = threadIdx.x & 31;
    int n = blockIdx.x * 8 + warp;
    int h = blockIdx.y;
    if (n >= N_NODES) return;
    int beg = g_rowptr[n], end = g_rowptr[n + 1];
    float ssrc = g_s1src[h * N_NODES + n];
    const __half* hb = g_h1h + (size_t)h * N_NODES * NHID;
    const float* sd = g_s1dst + (size_t)h * N_NODES;
    float ax = 0.f, ay = 0.f, rs = 0.f;
    for (int i = beg; i < end; ++i) {
        int v = __ldg(&g_dst_sorted[i]);
        float lg = ssrc + __ldg(&sd[v]);
        lg = lg > 0.f ? lg : ALPHA * lg;
        float e = __expf(-lg);
        rs += e;
        float2 hv = __half22float2(*(const __half2*)(hb + (size_t)v * NHID + lane * 2));
        ax = fmaf(e, hv.x, ax);
        ay = fmaf(e, hv.y, ay);
    }
    float inv = 1.f / rs;
    float o0 = ax * inv, o1 = ay * inv;
    o0 = o0 > 0.f ? o0 : expm1f(o0);
    o1 = o1 > 0.f ? o1 : expm1f(o1);
    *(__half2*)(g_hcath + (size_t)n * HCAT + h * NHID + lane * 2) =
        __floats2half2_rn(o0, o1);
}

// ---------------------------------------------------------------------------
// Layer-2 scores (16-dim dots, thread per node)
// ---------------------------------------------------------------------------
__global__ void k_scores2(const float* __restrict__ a2) {
    int n = blockIdx.x * blockDim.x + threadIdx.x;
    if (n >= N_NODES) return;
    float ps = 0.f, pd = 0.f;
    const float* hp = g_h2 + (size_t)n * NCLASS;
#pragma unroll
    for (int c = 0; c < NCLASS; ++c) {
        float v = hp[c];
        ps = fmaf(v, __ldg(&a2[c]), ps);
        pd = fmaf(v, __ldg(&a2[NCLASS + c]), pd);
    }
    g_s2src[n] = ps;
    g_s2dst[n] = pd;
}

// ---------------------------------------------------------------------------
// Layer-2 CSR aggregation: thread per (node, class)
// ---------------------------------------------------------------------------
__global__ __launch_bounds__(256) void k_agg2() {
    int t = blockIdx.x * blockDim.x + threadIdx.x;
    int n = t >> 4;
    int f = t & 15;
    if (n >= N_NODES) return;
    int beg = g_rowptr[n], end = g_rowptr[n + 1];
    float ss = g_s2src[n];
    float acc = 0.f, rs = 0.f;
    for (int i = beg; i < end; ++i) {
        int v = __ldg(&g_dst_sorted[i]);
        float lg = ss + __ldg(&g_s2dst[v]);
        lg = lg > 0.f ? lg : ALPHA * lg;
        float e = __expf(-lg);
        rs += e;
        acc = fmaf(e, __ldg(&g_h2[(size_t)v * NCLASS + f]), acc);
    }
    g_p2[(size_t)n * NCLASS + f] = acc / rs;
}

// ---------------------------------------------------------------------------
// elu + log_softmax over 16 classes, thread per node
// ---------------------------------------------------------------------------
__global__ void k_final(float* __restrict__ out) {
    int n = blockIdx.x * blockDim.x + threadIdx.x;
    if (n >= N_NODES) return;
    float v[NCLASS];
    float m = -1e30f;
#pragma unroll
    for (int c = 0; c < NCLASS; ++c) {
        float x = g_p2[(size_t)n * NCLASS + c];
        x = x > 0.f ? x : expm1f(x);
        v[c] = x;
        m = fmaxf(m, x);
    }
    float s = 0.f;
#pragma unroll
    for (int c = 0; c < NCLASS; ++c) s += __expf(v[c] - m);
    float l = m + logf(s);
#pragma unroll
    for (int c = 0; c < NCLASS; ++c) out[(size_t)n * NCLASS + c] = v[c] - l;
}

// ---------------------------------------------------------------------------
// Launch
// ---------------------------------------------------------------------------
extern "C" void kernel_launch(void* const* d_in, const int* in_sizes, int n_in,
                              void* d_out, int out_size) {
    const float* x  = (const float*)d_in[0];
    const int*   ei = (const int*)d_in[1];
    const float* W1 = (const float*)d_in[2];
    const float* a1 = (const float*)d_in[3];
    const float* W2 = (const float*)d_in[4];
    const float* a2 = (const float*)d_in[5];
    float* out = (float*)d_out;

    void* h1p = nullptr;
    cudaGetSymbolAddress(&h1p, g_h1h);

    // fp16 conversions
    k_cvt_x<<<((size_t)N_NODES * NFEAT / 8 + 255) / 256, 256>>>(x);
    k_cvt_w1<<<(H1 * NHID * NFEAT + 255) / 256, 256>>>(W1);
    k_cvt_w2<<<(NCLASS * HCAT + 255) / 256, 256>>>(W2);

    // CSR build
    k_zero_deg<<<(N_NODES + 255) / 256, 256>>>();
    k_degree<<<(N_EDGES + 255) / 256, 256>>>(ei);
    k_scan<<<1, 1024>>>();
    k_scatter<<<(N_EDGES + 255) / 256, 256>>>(ei);

    // Layer 1
    dim3 g1((N_NODES + 127) / 128, H1);
    k_gemm1<<<g1, 256>>>((__half*)h1p);
    dim3 gw((N_NODES + 7) / 8, H1);
    k_scores1<<<gw, 256>>>(a1);
    k_agg1<<<gw, 256>>>();

    // Layer 2
    k_gemm2<<<(N_NODES + 127) / 128, 256>>>();
    k_scores2<<<(N_NODES + 255) / 256, 256>>>(a2);
    k_agg2<<<(N_NODES * NCLASS + 255) / 256, 256>>>();
    k_final<<<(N_NODES + 255) / 256, 256>>>(out);
}

// round 9
// speedup vs baseline: 1.6654x; 1.3014x over previous
#include <cuda_runtime.h>
#include <cuda_fp16.h>
#include <cstdint>
#include <cstddef>

// ---------------------------------------------------------------------------
// Problem constants (fixed by the dataset)
// ---------------------------------------------------------------------------
#define N_NODES 50000
#define N_EDGES 1600000
#define NFEAT   512
#define NHID    64
#define H1      8
#define NCLASS  16
#define HCAT    (H1 * NHID)   // 512
#define ALPHA   0.2f

// ---------------------------------------------------------------------------
// Scratch (device globals; no allocation allowed)
// ---------------------------------------------------------------------------
__device__ __half g_xh[(size_t)N_NODES * NFEAT];        // x in fp16
__device__ __half g_w1t[(size_t)H1 * NHID * NFEAT];     // W1^T fp16: [h][n][k]
__device__ __half g_w2t[(size_t)NCLASS * HCAT];         // W2^T fp16: [n][k]
__device__ __half g_h1h[(size_t)N_NODES * HCAT];        // layer1 feats [n][h][f] fp16
__device__ __half g_hcath[(size_t)N_NODES * HCAT];      // concat(elu(h')) fp16
__device__ float g_h2[(size_t)N_NODES * NCLASS];        // layer2 linear (fp32)
__device__ float g_p2[(size_t)N_NODES * NCLASS];        // layer2 aggregated
__device__ float g_s1src[N_NODES * H1];                 // [n][h] interleaved
__device__ float g_s1dst[N_NODES * H1];                 // [n][h] interleaved
__device__ float g_s2src[N_NODES];
__device__ float g_s2dst[N_NODES];
__device__ int   g_deg[N_NODES];
__device__ int   g_rowptr[N_NODES + 1];
__device__ int   g_fill[N_NODES];
__device__ int   g_dst_sorted[N_EDGES];

// ---------------------------------------------------------------------------
// helpers
// ---------------------------------------------------------------------------
__device__ __forceinline__ uint32_t packh2(float lo, float hi) {
    __half2 h = __floats2half2_rn(lo, hi);
    return *(uint32_t*)&h;
}

__device__ __forceinline__ void mma_fp16(float4& d,
                                         uint32_t a0, uint32_t a1,
                                         uint32_t a2, uint32_t a3,
                                         uint32_t b0, uint32_t b1) {
    asm volatile(
        "mma.sync.aligned.m16n8k16.row.col.f32.f16.f16.f32 "
        "{%0,%1,%2,%3}, {%4,%5,%6,%7}, {%8,%9}, {%0,%1,%2,%3};"
        : "+f"(d.x), "+f"(d.y), "+f"(d.z), "+f"(d.w)
        : "r"(a0), "r"(a1), "r"(a2), "r"(a3), "r"(b0), "r"(b1));
}

// ---------------------------------------------------------------------------
// fp16 conversion kernels
// ---------------------------------------------------------------------------
__global__ void k_cvt_x(const float* __restrict__ x) {
    size_t i = ((size_t)blockIdx.x * blockDim.x + threadIdx.x) * 8;
    if (i >= (size_t)N_NODES * NFEAT) return;
    float4 a = *(const float4*)(x + i);
    float4 b = *(const float4*)(x + i + 4);
    uint4 u;
    u.x = packh2(a.x, a.y); u.y = packh2(a.z, a.w);
    u.z = packh2(b.x, b.y); u.w = packh2(b.z, b.w);
    *(uint4*)&g_xh[i] = u;
}

__global__ void k_cvt_w1(const float* __restrict__ W1) {
    int idx = blockIdx.x * blockDim.x + threadIdx.x;
    if (idx >= H1 * NHID * NFEAT) return;
    int k = idx & (NFEAT - 1);
    int n = (idx >> 9) & (NHID - 1);
    int h = idx >> 15;
    g_w1t[idx] = __float2half(W1[(size_t)h * NFEAT * NHID + (size_t)k * NHID + n]);
}

__global__ void k_cvt_w2(const float* __restrict__ W2) {
    int idx = blockIdx.x * blockDim.x + threadIdx.x;
    if (idx >= NCLASS * HCAT) return;
    int k = idx & (HCAT - 1);
    int n = idx >> 9;
    g_w2t[idx] = __float2half(W2[(size_t)k * NCLASS + n]);
}

// ---------------------------------------------------------------------------
// CSR construction
// ---------------------------------------------------------------------------
__global__ void k_zero_deg() {
    int i = blockIdx.x * blockDim.x + threadIdx.x;
    if (i < N_NODES) g_deg[i] = 0;
}

__global__ void k_degree(const int* __restrict__ ei) {
    int e = blockIdx.x * blockDim.x + threadIdx.x;
    if (e < N_EDGES) atomicAdd(&g_deg[ei[e]], 1);
}

__global__ __launch_bounds__(1024) void k_scan() {
    __shared__ int sums[1024];
    int tid = threadIdx.x;
    constexpr int CH = (N_NODES + 1023) / 1024;  // 49
    int start = tid * CH;
    int end = min(start + CH, N_NODES);
    int s = 0;
    for (int i = start; i < end; ++i) s += g_deg[i];
    sums[tid] = s;
    __syncthreads();
    for (int off = 1; off < 1024; off <<= 1) {
        int t = (tid >= off) ? sums[tid - off] : 0;
        __syncthreads();
        sums[tid] += t;
        __syncthreads();
    }
    int running = sums[tid] - s;
    for (int i = start; i < end; ++i) {
        g_rowptr[i] = running;
        g_fill[i]   = running;
        running += g_deg[i];
    }
    if (tid == 1023) g_rowptr[N_NODES] = sums[1023];
}

__global__ void k_scatter(const int* __restrict__ ei) {
    int e = blockIdx.x * blockDim.x + threadIdx.x;
    if (e < N_EDGES) {
        int s = ei[e];
        int d = ei[N_EDGES + e];
        int pos = atomicAdd(&g_fill[s], 1);
        g_dst_sorted[pos] = d;
    }
}

// ---------------------------------------------------------------------------
// Layer-1 GEMM: fp16 MMA m16n8k16, software-pipelined global loads.
// Output layout: g_h1h[n][h*64 + c]  (all heads interleaved per node)
// BM=128, BN=64, BK=32, 256 threads = 8 warps (4m x 2n), warp tile 32x32.
// ---------------------------------------------------------------------------
#define G1_STR 40

__global__ __launch_bounds__(256) void k_gemm1() {
    constexpr int BM = 128, BN = 64, BK = 32, K = NFEAT;
    __shared__ __half As[BM * G1_STR];
    __shared__ __half Bs[BN * G1_STR];

    int h = blockIdx.y;
    const __half* A = g_xh;
    const __half* B = g_w1t + (size_t)h * NHID * NFEAT;

    int m0 = blockIdx.x * BM;
    int tid = threadIdx.x;
    int warp = tid >> 5;
    int lane = tid & 31;
    int g = lane >> 2;
    int t = lane & 3;
    int wm = warp >> 1;       // 0..3
    int wn = warp & 1;        // 0..1

    int aRow = tid >> 1;                // 0..127
    int aCol = (tid & 1) * 16;          // 0 or 16
    int bRow = tid >> 2;                // 0..63
    int bCol = (tid & 3) * 8;           // 0,8,16,24
    const bool aValid = (m0 + aRow) < N_NODES;
    const __half* Aptr = A + (size_t)(m0 + aRow) * K + aCol;
    const __half* Bptr = B + (size_t)bRow * K + bCol;

    float4 acc[2][4];
#pragma unroll
    for (int mi = 0; mi < 2; ++mi)
#pragma unroll
        for (int nj = 0; nj < 4; ++nj)
            acc[mi][nj] = make_float4(0.f, 0.f, 0.f, 0.f);

    uint4 ra0, ra1, rb;
    ra0 = aValid ? *(const uint4*)(Aptr) : make_uint4(0, 0, 0, 0);
    ra1 = aValid ? *(const uint4*)(Aptr + 8) : make_uint4(0, 0, 0, 0);
    rb  = *(const uint4*)(Bptr);

    for (int k0 = 0; k0 < K; k0 += BK) {
        __syncthreads();
        *(uint4*)&As[aRow * G1_STR + aCol]     = ra0;
        *(uint4*)&As[aRow * G1_STR + aCol + 8] = ra1;
        *(uint4*)&Bs[bRow * G1_STR + bCol]     = rb;
        __syncthreads();
        if (k0 + BK < K) {
            ra0 = aValid ? *(const uint4*)(Aptr + k0 + BK) : make_uint4(0, 0, 0, 0);
            ra1 = aValid ? *(const uint4*)(Aptr + k0 + BK + 8) : make_uint4(0, 0, 0, 0);
            rb  = *(const uint4*)(Bptr + k0 + BK);
        }
#pragma unroll
        for (int kk = 0; kk < BK; kk += 16) {
            uint32_t af[2][4];
#pragma unroll
            for (int mi = 0; mi < 2; ++mi) {
                int r = (wm * 32 + mi * 16 + g) * G1_STR + kk + 2 * t;
                af[mi][0] = *(const uint32_t*)&As[r];
                af[mi][1] = *(const uint32_t*)&As[r + 8 * G1_STR];
                af[mi][2] = *(const uint32_t*)&As[r + 8];
                af[mi][3] = *(const uint32_t*)&As[r + 8 * G1_STR + 8];
            }
            uint32_t bf[4][2];
#pragma unroll
            for (int nj = 0; nj < 4; ++nj) {
                int r = (wn * 32 + nj * 8 + g) * G1_STR + kk + 2 * t;
                bf[nj][0] = *(const uint32_t*)&Bs[r];
                bf[nj][1] = *(const uint32_t*)&Bs[r + 8];
            }
#pragma unroll
            for (int mi = 0; mi < 2; ++mi)
#pragma unroll
                for (int nj = 0; nj < 4; ++nj)
                    mma_fp16(acc[mi][nj],
                             af[mi][0], af[mi][1], af[mi][2], af[mi][3],
                             bf[nj][0], bf[nj][1]);
        }
    }

    // Epilogue -> interleaved layout [n][h*64 + c]
#pragma unroll
    for (int mi = 0; mi < 2; ++mi) {
#pragma unroll
        for (int nj = 0; nj < 4; ++nj) {
            int r = m0 + wm * 32 + mi * 16 + g;
            int c = h * NHID + wn * 32 + nj * 8 + t * 2;
            float4 v = acc[mi][nj];
            if (r < N_NODES) {
                uint32_t p = packh2(v.x, v.y);
                *(uint32_t*)&g_h1h[(size_t)r * HCAT + c] = p;
            }
            if (r + 8 < N_NODES) {
                uint32_t p = packh2(v.z, v.w);
                *(uint32_t*)&g_h1h[(size_t)(r + 8) * HCAT + c] = p;
            }
        }
    }
}

// ---------------------------------------------------------------------------
// Layer-2 GEMM: fp16 MMA, BN=16 (no wasted columns).
// h2[M,16] = hcath[M,512] @ W2t[16,512]^T, fp32 out.
// ---------------------------------------------------------------------------
__global__ __launch_bounds__(256) void k_gemm2() {
    constexpr int BM = 128, BK = 32, K = HCAT;
    __shared__ __half As[BM * G1_STR];
    __shared__ __half Bs[NCLASS * G1_STR];

    int m0 = blockIdx.x * BM;
    int tid = threadIdx.x;
    int warp = tid >> 5;
    int lane = tid & 31;
    int g = lane >> 2;
    int t = lane & 3;

    int aRow = tid >> 1;
    int aCol = (tid & 1) * 16;
    const bool aValid = (m0 + aRow) < N_NODES;
    const __half* Aptr = g_hcath + (size_t)(m0 + aRow) * K + aCol;
    int bRow = tid >> 2;            // 0..63, valid < 16
    int bCol = (tid & 3) * 8;
    const bool bAct = bRow < NCLASS;
    const __half* Bptr = g_w2t + (size_t)bRow * K + bCol;

    float4 acc[2];
    acc[0] = make_float4(0.f, 0.f, 0.f, 0.f);
    acc[1] = make_float4(0.f, 0.f, 0.f, 0.f);

    uint4 ra0, ra1, rb;
    ra0 = aValid ? *(const uint4*)(Aptr) : make_uint4(0, 0, 0, 0);
    ra1 = aValid ? *(const uint4*)(Aptr + 8) : make_uint4(0, 0, 0, 0);
    rb  = bAct ? *(const uint4*)(Bptr) : make_uint4(0, 0, 0, 0);

    for (int k0 = 0; k0 < K; k0 += BK) {
        __syncthreads();
        *(uint4*)&As[aRow * G1_STR + aCol]     = ra0;
        *(uint4*)&As[aRow * G1_STR + aCol + 8] = ra1;
        if (bAct) *(uint4*)&Bs[bRow * G1_STR + bCol] = rb;
        __syncthreads();
        if (k0 + BK < K) {
            ra0 = aValid ? *(const uint4*)(Aptr + k0 + BK) : make_uint4(0, 0, 0, 0);
            ra1 = aValid ? *(const uint4*)(Aptr + k0 + BK + 8) : make_uint4(0, 0, 0, 0);
            rb  = bAct ? *(const uint4*)(Bptr + k0 + BK) : make_uint4(0, 0, 0, 0);
        }
#pragma unroll
        for (int kk = 0; kk < BK; kk += 16) {
            int r = (warp * 16 + g) * G1_STR + kk + 2 * t;
            uint32_t a0 = *(const uint32_t*)&As[r];
            uint32_t a1 = *(const uint32_t*)&As[r + 8 * G1_STR];
            uint32_t a2 = *(const uint32_t*)&As[r + 8];
            uint32_t a3 = *(const uint32_t*)&As[r + 8 * G1_STR + 8];
#pragma unroll
            for (int nj = 0; nj < 2; ++nj) {
                int rb2 = (nj * 8 + g) * G1_STR + kk + 2 * t;
                uint32_t b0 = *(const uint32_t*)&Bs[rb2];
                uint32_t b1 = *(const uint32_t*)&Bs[rb2 + 8];
                mma_fp16(acc[nj], a0, a1, a2, a3, b0, b1);
            }
        }
    }

#pragma unroll
    for (int nj = 0; nj < 2; ++nj) {
        int r = m0 + warp * 16 + g;
        int c = nj * 8 + t * 2;
        float4 v = acc[nj];
        if (r < N_NODES)
            *(float2*)&g_h2[(size_t)r * NCLASS + c] = make_float2(v.x, v.y);
        if (r + 8 < N_NODES)
            *(float2*)&g_h2[(size_t)(r + 8) * NCLASS + c] = make_float2(v.z, v.w);
    }
}

// ---------------------------------------------------------------------------
// Layer-1 scores, all heads fused: warp per node.
// lane: head = lane>>2, quarter q = lane&3 (16 feats).
// Output interleaved: g_s1src/[n*8+h]
// ---------------------------------------------------------------------------
__global__ __launch_bounds__(256) void k_scores1(const float* __restrict__ a1) {
    int warp = threadIdx.x >> 5;
    int lane = threadIdx.x & 31;
    int n = blockIdx.x * 8 + warp;
    if (n >= N_NODES) return;
    int head = lane >> 2;
    int q = lane & 3;

    const __half* hp = g_h1h + (size_t)n * HCAT + lane * 16;
    uint4 u0 = *(const uint4*)(hp);
    uint4 u1 = *(const uint4*)(hp + 8);
    float f[16];
    {
        const __half2* c0 = (const __half2*)&u0;
        const __half2* c1 = (const __half2*)&u1;
#pragma unroll
        for (int j = 0; j < 4; ++j) {
            float2 p = __half22float2(c0[j]);
            f[2 * j] = p.x; f[2 * j + 1] = p.y;
            float2 r = __half22float2(c1[j]);
            f[8 + 2 * j] = r.x; f[8 + 2 * j + 1] = r.y;
        }
    }
    const float* as = a1 + head * (2 * NHID) + q * 16;
    const float* ad = as + NHID;
    float ps = 0.f, pd = 0.f;
#pragma unroll
    for (int j = 0; j < 16; ++j) {
        ps = fmaf(f[j], __ldg(&as[j]), ps);
        pd = fmaf(f[j], __ldg(&ad[j]), pd);
    }
    // reduce within 4-lane group
    ps += __shfl_xor_sync(0xFFFFFFFFu, ps, 1);
    pd += __shfl_xor_sync(0xFFFFFFFFu, pd, 1);
    ps += __shfl_xor_sync(0xFFFFFFFFu, ps, 2);
    pd += __shfl_xor_sync(0xFFFFFFFFu, pd, 2);
    if (q == 0) {
        g_s1src[n * H1 + head] = ps;
        g_s1dst[n * H1 + head] = pd;
    }
}

// ---------------------------------------------------------------------------
// Layer-1 CSR aggregation, ALL 8 HEADS fused: warp per node.
// lane: head = lane>>2, 16 fp32 accumulators per lane.
// Per edge: 1 LDG idx + 1 LDG score + 2 LDG.128 features (vs 24 before).
// ---------------------------------------------------------------------------
__global__ __launch_bounds__(256) void k_agg1() {
    int warp = threadIdx.x >> 5;
    int lane = threadIdx.x & 31;
    int n = blockIdx.x * 8 + warp;
    if (n >= N_NODES) return;
    int head = lane >> 2;
    int beg = g_rowptr[n], end = g_rowptr[n + 1];
    float ssrc = __ldg(&g_s1src[n * H1 + head]);

    float af[16];
#pragma unroll
    for (int j = 0; j < 16; ++j) af[j] = 0.f;
    float rs = 0.f;

    // software pipeline: prefetch idx+score one iteration ahead
    int v = 0; float sdv = 0.f;
    if (beg < end) {
        v = __ldg(&g_dst_sorted[beg]);
        sdv = __ldg(&g_s1dst[v * H1 + head]);
    }
    for (int i = beg; i < end; ++i) {
        int vn = 0; float sdn = 0.f;
        if (i + 1 < end) {
            vn = __ldg(&g_dst_sorted[i + 1]);
            sdn = __ldg(&g_s1dst[vn * H1 + head]);
        }
        float lg = ssrc + sdv;
        lg = lg > 0.f ? lg : ALPHA * lg;
        float e = __expf(-lg);
        rs += e;
        const __half* hp = g_h1h + (size_t)v * HCAT + lane * 16;
        uint4 u0 = *(const uint4*)(hp);
        uint4 u1 = *(const uint4*)(hp + 8);
        const __half2* c0 = (const __half2*)&u0;
        const __half2* c1 = (const __half2*)&u1;
#pragma unroll
        for (int j = 0; j < 4; ++j) {
            float2 p = __half22float2(c0[j]);
            af[2 * j]     = fmaf(e, p.x, af[2 * j]);
            af[2 * j + 1] = fmaf(e, p.y, af[2 * j + 1]);
            float2 r = __half22float2(c1[j]);
            af[8 + 2 * j]     = fmaf(e, r.x, af[8 + 2 * j]);
            af[8 + 2 * j + 1] = fmaf(e, r.y, af[8 + 2 * j + 1]);
        }
        v = vn; sdv = sdn;
    }

    float inv = 1.f / rs;
    __half2 oh[8];
#pragma unroll
    for (int j = 0; j < 8; ++j) {
        float o0 = af[2 * j] * inv;
        float o1 = af[2 * j + 1] * inv;
        o0 = o0 > 0.f ? o0 : expm1f(o0);
        o1 = o1 > 0.f ? o1 : expm1f(o1);
        oh[j] = __floats2half2_rn(o0, o1);
    }
    __half* op = g_hcath + (size_t)n * HCAT + lane * 16;
    *(uint4*)(op)     = *(uint4*)&oh[0];
    *(uint4*)(op + 8) = *(uint4*)&oh[4];
}

// ---------------------------------------------------------------------------
// Layer-2 scores (16-dim dots, thread per node)
// ---------------------------------------------------------------------------
__global__ void k_scores2(const float* __restrict__ a2) {
    int n = blockIdx.x * blockDim.x + threadIdx.x;
    if (n >= N_NODES) return;
    float ps = 0.f, pd = 0.f;
    const float* hp = g_h2 + (size_t)n * NCLASS;
#pragma unroll
    for (int c = 0; c < NCLASS; ++c) {
        float v = hp[c];
        ps = fmaf(v, __ldg(&a2[c]), ps);
        pd = fmaf(v, __ldg(&a2[NCLASS + c]), pd);
    }
    g_s2src[n] = ps;
    g_s2dst[n] = pd;
}

// ---------------------------------------------------------------------------
// Layer-2 CSR aggregation: thread per (node, class)
// ---------------------------------------------------------------------------
__global__ __launch_bounds__(256) void k_agg2() {
    int t = blockIdx.x * blockDim.x + threadIdx.x;
    int n = t >> 4;
    int f = t & 15;
    if (n >= N_NODES) return;
    int beg = g_rowptr[n], end = g_rowptr[n + 1];
    float ss = g_s2src[n];
    float acc = 0.f, rs = 0.f;
    for (int i = beg; i < end; ++i) {
        int v = __ldg(&g_dst_sorted[i]);
        float lg = ss + __ldg(&g_s2dst[v]);
        lg = lg > 0.f ? lg : ALPHA * lg;
        float e = __expf(-lg);
        rs += e;
        acc = fmaf(e, __ldg(&g_h2[(size_t)v * NCLASS + f]), acc);
    }
    g_p2[(size_t)n * NCLASS + f] = acc / rs;
}

// ---------------------------------------------------------------------------
// elu + log_softmax over 16 classes, thread per node
// ---------------------------------------------------------------------------
__global__ void k_final(float* __restrict__ out) {
    int n = blockIdx.x * blockDim.x + threadIdx.x;
    if (n >= N_NODES) return;
    float v[NCLASS];
    float m = -1e30f;
#pragma unroll
    for (int c = 0; c < NCLASS; ++c) {
        float x = g_p2[(size_t)n * NCLASS + c];
        x = x > 0.f ? x : expm1f(x);
        v[c] = x;
        m = fmaxf(m, x);
    }
    float s = 0.f;
#pragma unroll
    for (int c = 0; c < NCLASS; ++c) s += __expf(v[c] - m);
    float l = m + logf(s);
#pragma unroll
    for (int c = 0; c < NCLASS; ++c) out[(size_t)n * NCLASS + c] = v[c] - l;
}

// ---------------------------------------------------------------------------
// Launch
// ---------------------------------------------------------------------------
extern "C" void kernel_launch(void* const* d_in, const int* in_sizes, int n_in,
                              void* d_out, int out_size) {
    const float* x  = (const float*)d_in[0];
    const int*   ei = (const int*)d_in[1];
    const float* W1 = (const float*)d_in[2];
    const float* a1 = (const float*)d_in[3];
    const float* W2 = (const float*)d_in[4];
    const float* a2 = (const float*)d_in[5];
    float* out = (float*)d_out;

    // fp16 conversions
    k_cvt_x<<<((size_t)N_NODES * NFEAT / 8 + 255) / 256, 256>>>(x);
    k_cvt_w1<<<(H1 * NHID * NFEAT + 255) / 256, 256>>>(W1);
    k_cvt_w2<<<(NCLASS * HCAT + 255) / 256, 256>>>(W2);

    // CSR build
    k_zero_deg<<<(N_NODES + 255) / 256, 256>>>();
    k_degree<<<(N_EDGES + 255) / 256, 256>>>(ei);
    k_scan<<<1, 1024>>>();
    k_scatter<<<(N_EDGES + 255) / 256, 256>>>(ei);

    // Layer 1
    dim3 g1((N_NODES + 127) / 128, H1);
    k_gemm1<<<g1, 256>>>();
    int nwb = (N_NODES + 7) / 8;
    k_scores1<<<nwb, 256>>>(a1);
    k_agg1<<<nwb, 256>>>();

    // Layer 2
    k_gemm2<<<(N_NODES + 127) / 128, 256>>>();
    k_scores2<<<(N_NODES + 255) / 256, 256>>>(a2);
    k_agg2<<<(N_NODES * NCLASS + 255) / 256, 256>>>();
    k_final<<<(N_NODES + 255) / 256, 256>>>(out);
}

// round 12
// speedup vs baseline: 1.7810x; 1.0694x over previous
#include <cuda_runtime.h>
#include <cuda_fp16.h>
#include <cstdint>
#include <cstddef>

// ---------------------------------------------------------------------------
// Problem constants (fixed by the dataset)
// ---------------------------------------------------------------------------
#define N_NODES 50000
#define N_EDGES 1600000
#define NFEAT   512
#define NHID    64
#define H1      8
#define NCLASS  16
#define HCAT    (H1 * NHID)   // 512
#define ALPHA   0.2f

// ---------------------------------------------------------------------------
// Scratch (device globals; no allocation allowed)
// ---------------------------------------------------------------------------
__device__ __half g_xh[(size_t)N_NODES * NFEAT];        // x in fp16
__device__ __half g_w1t[(size_t)H1 * NHID * NFEAT];     // W1^T fp16: [h][n][k]
__device__ __half g_w2t[(size_t)NCLASS * HCAT];         // W2^T fp16: [n][k]
__device__ __half g_h1h[(size_t)N_NODES * HCAT];        // layer1 feats [n][h][f] fp16
__device__ __half g_hcath[(size_t)N_NODES * HCAT];      // concat(elu(h')) fp16
__device__ float g_h2[(size_t)N_NODES * NCLASS];        // layer2 linear (fp32)
__device__ float g_s1src[N_NODES * H1];                 // [n][h] interleaved
__device__ float g_s1dst[N_NODES * H1];                 // [n][h] interleaved
__device__ float g_s2src[N_NODES];
__device__ float g_s2dst[N_NODES];
__device__ int   g_deg[N_NODES];
__device__ int   g_rowptr[N_NODES + 1];
__device__ int   g_rank[N_EDGES];
__device__ int   g_dst_sorted[N_EDGES];

// ---------------------------------------------------------------------------
// helpers
// ---------------------------------------------------------------------------
__device__ __forceinline__ uint32_t packh2(float lo, float hi) {
    __half2 h = __floats2half2_rn(lo, hi);
    return *(uint32_t*)&h;
}

__device__ __forceinline__ void mma_fp16(float4& d,
                                         uint32_t a0, uint32_t a1,
                                         uint32_t a2, uint32_t a3,
                                         uint32_t b0, uint32_t b1) {
    asm volatile(
        "mma.sync.aligned.m16n8k16.row.col.f32.f16.f16.f32 "
        "{%0,%1,%2,%3}, {%4,%5,%6,%7}, {%8,%9}, {%0,%1,%2,%3};"
        : "+f"(d.x), "+f"(d.y), "+f"(d.z), "+f"(d.w)
        : "r"(a0), "r"(a1), "r"(a2), "r"(a3), "r"(b0), "r"(b1));
}

// ---------------------------------------------------------------------------
// fp16 conversion kernels
// ---------------------------------------------------------------------------
__global__ void k_cvt_x(const float* __restrict__ x) {
    size_t i = ((size_t)blockIdx.x * blockDim.x + threadIdx.x) * 8;
    if (i >= (size_t)N_NODES * NFEAT) return;
    float4 a = *(const float4*)(x + i);
    float4 b = *(const float4*)(x + i + 4);
    uint4 u;
    u.x = packh2(a.x, a.y); u.y = packh2(a.z, a.w);
    u.z = packh2(b.x, b.y); u.w = packh2(b.z, b.w);
    *(uint4*)&g_xh[i] = u;
}

__global__ void k_cvt_w1(const float* __restrict__ W1) {
    int idx = blockIdx.x * blockDim.x + threadIdx.x;
    if (idx >= H1 * NHID * NFEAT) return;
    int k = idx & (NFEAT - 1);
    int n = (idx >> 9) & (NHID - 1);
    int h = idx >> 15;
    g_w1t[idx] = __float2half(W1[(size_t)h * NFEAT * NHID + (size_t)k * NHID + n]);
}

__global__ void k_cvt_w2(const float* __restrict__ W2) {
    int idx = blockIdx.x * blockDim.x + threadIdx.x;
    if (idx >= NCLASS * HCAT) return;
    int k = idx & (HCAT - 1);
    int n = idx >> 9;
    g_w2t[idx] = __float2half(W2[(size_t)k * NCLASS + n]);
}

// ---------------------------------------------------------------------------
// CSR construction (rank saved in degree pass -> atomic-free scatter)
// ---------------------------------------------------------------------------
__global__ void k_degree(const int* __restrict__ ei) {
    int e = blockIdx.x * blockDim.x + threadIdx.x;
    if (e < N_EDGES) {
        int r = atomicAdd(&g_deg[ei[e]], 1);
        g_rank[e] = r;
    }
}

__global__ __launch_bounds__(1024) void k_scan() {
    __shared__ int sums[1024];
    int tid = threadIdx.x;
    constexpr int CH = (N_NODES + 1023) / 1024;  // 49
    int start = tid * CH;
    int end = min(start + CH, N_NODES);
    int s = 0;
    for (int i = start; i < end; ++i) s += g_deg[i];
    sums[tid] = s;
    __syncthreads();
    for (int off = 1; off < 1024; off <<= 1) {
        int t = (tid >= off) ? sums[tid - off] : 0;
        __syncthreads();
        sums[tid] += t;
        __syncthreads();
    }
    int running = sums[tid] - s;
    for (int i = start; i < end; ++i) {
        g_rowptr[i] = running;
        running += g_deg[i];
    }
    if (tid == 1023) g_rowptr[N_NODES] = sums[1023];
}

__global__ void k_scatter(const int* __restrict__ ei) {
    int e = blockIdx.x * blockDim.x + threadIdx.x;
    if (e < N_EDGES) {
        int s = ei[e];
        int d = ei[N_EDGES + e];
        g_dst_sorted[g_rowptr[s] + g_rank[e]] = d;
    }
}

// ---------------------------------------------------------------------------
// Layer-1 GEMM: fp16 MMA m16n8k16, software-pipelined global loads.
// Output layout: g_h1h[n][h*64 + c]  (all heads interleaved per node)
// BM=128, BN=64, BK=32, 256 threads = 8 warps (4m x 2n), warp tile 32x32.
// ---------------------------------------------------------------------------
#define G1_STR 40

__global__ __launch_bounds__(256) void k_gemm1() {
    constexpr int BM = 128, BN = 64, BK = 32, K = NFEAT;
    __shared__ __half As[BM * G1_STR];
    __shared__ __half Bs[BN * G1_STR];

    int h = blockIdx.y;
    const __half* A = g_xh;
    const __half* B = g_w1t + (size_t)h * NHID * NFEAT;

    int m0 = blockIdx.x * BM;
    int tid = threadIdx.x;
    int warp = tid >> 5;
    int lane = tid & 31;
    int g = lane >> 2;
    int t = lane & 3;
    int wm = warp >> 1;       // 0..3
    int wn = warp & 1;        // 0..1

    int aRow = tid >> 1;                // 0..127
    int aCol = (tid & 1) * 16;          // 0 or 16
    int bRow = tid >> 2;                // 0..63
    int bCol = (tid & 3) * 8;           // 0,8,16,24
    const bool aValid = (m0 + aRow) < N_NODES;
    const __half* Aptr = A + (size_t)(m0 + aRow) * K + aCol;
    const __half* Bptr = B + (size_t)bRow * K + bCol;

    float4 acc[2][4];
#pragma unroll
    for (int mi = 0; mi < 2; ++mi)
#pragma unroll
        for (int nj = 0; nj < 4; ++nj)
            acc[mi][nj] = make_float4(0.f, 0.f, 0.f, 0.f);

    uint4 ra0, ra1, rb;
    ra0 = aValid ? *(const uint4*)(Aptr) : make_uint4(0, 0, 0, 0);
    ra1 = aValid ? *(const uint4*)(Aptr + 8) : make_uint4(0, 0, 0, 0);
    rb  = *(const uint4*)(Bptr);

    for (int k0 = 0; k0 < K; k0 += BK) {
        __syncthreads();
        *(uint4*)&As[aRow * G1_STR + aCol]     = ra0;
        *(uint4*)&As[aRow * G1_STR + aCol + 8] = ra1;
        *(uint4*)&Bs[bRow * G1_STR + bCol]     = rb;
        __syncthreads();
        if (k0 + BK < K) {
            ra0 = aValid ? *(const uint4*)(Aptr + k0 + BK) : make_uint4(0, 0, 0, 0);
            ra1 = aValid ? *(const uint4*)(Aptr + k0 + BK + 8) : make_uint4(0, 0, 0, 0);
            rb  = *(const uint4*)(Bptr + k0 + BK);
        }
#pragma unroll
        for (int kk = 0; kk < BK; kk += 16) {
            uint32_t af[2][4];
#pragma unroll
            for (int mi = 0; mi < 2; ++mi) {
                int r = (wm * 32 + mi * 16 + g) * G1_STR + kk + 2 * t;
                af[mi][0] = *(const uint32_t*)&As[r];
                af[mi][1] = *(const uint32_t*)&As[r + 8 * G1_STR];
                af[mi][2] = *(const uint32_t*)&As[r + 8];
                af[mi][3] = *(const uint32_t*)&As[r + 8 * G1_STR + 8];
            }
            uint32_t bf[4][2];
#pragma unroll
            for (int nj = 0; nj < 4; ++nj) {
                int r = (wn * 32 + nj * 8 + g) * G1_STR + kk + 2 * t;
                bf[nj][0] = *(const uint32_t*)&Bs[r];
                bf[nj][1] = *(const uint32_t*)&Bs[r + 8];
            }
#pragma unroll
            for (int mi = 0; mi < 2; ++mi)
#pragma unroll
                for (int nj = 0; nj < 4; ++nj)
                    mma_fp16(acc[mi][nj],
                             af[mi][0], af[mi][1], af[mi][2], af[mi][3],
                             bf[nj][0], bf[nj][1]);
        }
    }

    // Epilogue -> interleaved layout [n][h*64 + c]
#pragma unroll
    for (int mi = 0; mi < 2; ++mi) {
#pragma unroll
        for (int nj = 0; nj < 4; ++nj) {
            int r = m0 + wm * 32 + mi * 16 + g;
            int c = h * NHID + wn * 32 + nj * 8 + t * 2;
            float4 v = acc[mi][nj];
            if (r < N_NODES) {
                uint32_t p = packh2(v.x, v.y);
                *(uint32_t*)&g_h1h[(size_t)r * HCAT + c] = p;
            }
            if (r + 8 < N_NODES) {
                uint32_t p = packh2(v.z, v.w);
                *(uint32_t*)&g_h1h[(size_t)(r + 8) * HCAT + c] = p;
            }
        }
    }
}

// ---------------------------------------------------------------------------
// Layer-2 GEMM: fp16 MMA, BN=16 (no wasted columns).
// ---------------------------------------------------------------------------
__global__ __launch_bounds__(256) void k_gemm2() {
    constexpr int BM = 128, BK = 32, K = HCAT;
    __shared__ __half As[BM * G1_STR];
    __shared__ __half Bs[NCLASS * G1_STR];

    int m0 = blockIdx.x * BM;
    int tid = threadIdx.x;
    int warp = tid >> 5;
    int lane = tid & 31;
    int g = lane >> 2;
    int t = lane & 3;

    int aRow = tid >> 1;
    int aCol = (tid & 1) * 16;
    const bool aValid = (m0 + aRow) < N_NODES;
    const __half* Aptr = g_hcath + (size_t)(m0 + aRow) * K + aCol;
    int bRow = tid >> 2;            // 0..63, valid < 16
    int bCol = (tid & 3) * 8;
    const bool bAct = bRow < NCLASS;
    const __half* Bptr = g_w2t + (size_t)bRow * K + bCol;

    float4 acc[2];
    acc[0] = make_float4(0.f, 0.f, 0.f, 0.f);
    acc[1] = make_float4(0.f, 0.f, 0.f, 0.f);

    uint4 ra0, ra1, rb;
    ra0 = aValid ? *(const uint4*)(Aptr) : make_uint4(0, 0, 0, 0);
    ra1 = aValid ? *(const uint4*)(Aptr + 8) : make_uint4(0, 0, 0, 0);
    rb  = bAct ? *(const uint4*)(Bptr) : make_uint4(0, 0, 0, 0);

    for (int k0 = 0; k0 < K; k0 += BK) {
        __syncthreads();
        *(uint4*)&As[aRow * G1_STR + aCol]     = ra0;
        *(uint4*)&As[aRow * G1_STR + aCol + 8] = ra1;
        if (bAct) *(uint4*)&Bs[bRow * G1_STR + bCol] = rb;
        __syncthreads();
        if (k0 + BK < K) {
            ra0 = aValid ? *(const uint4*)(Aptr + k0 + BK) : make_uint4(0, 0, 0, 0);
            ra1 = aValid ? *(const uint4*)(Aptr + k0 + BK + 8) : make_uint4(0, 0, 0, 0);
            rb  = bAct ? *(const uint4*)(Bptr + k0 + BK) : make_uint4(0, 0, 0, 0);
        }
#pragma unroll
        for (int kk = 0; kk < BK; kk += 16) {
            int r = (warp * 16 + g) * G1_STR + kk + 2 * t;
            uint32_t a0 = *(const uint32_t*)&As[r];
            uint32_t a1 = *(const uint32_t*)&As[r + 8 * G1_STR];
            uint32_t a2 = *(const uint32_t*)&As[r + 8];
            uint32_t a3 = *(const uint32_t*)&As[r + 8 * G1_STR + 8];
#pragma unroll
            for (int nj = 0; nj < 2; ++nj) {
                int rb2 = (nj * 8 + g) * G1_STR + kk + 2 * t;
                uint32_t b0 = *(const uint32_t*)&Bs[rb2];
                uint32_t b1 = *(const uint32_t*)&Bs[rb2 + 8];
                mma_fp16(acc[nj], a0, a1, a2, a3, b0, b1);
            }
        }
    }

#pragma unroll
    for (int nj = 0; nj < 2; ++nj) {
        int r = m0 + warp * 16 + g;
        int c = nj * 8 + t * 2;
        float4 v = acc[nj];
        if (r < N_NODES)
            *(float2*)&g_h2[(size_t)r * NCLASS + c] = make_float2(v.x, v.y);
        if (r + 8 < N_NODES)
            *(float2*)&g_h2[(size_t)(r + 8) * NCLASS + c] = make_float2(v.z, v.w);
    }
}

// ---------------------------------------------------------------------------
// Layer-1 scores, all heads fused: warp per node.
// ---------------------------------------------------------------------------
__global__ __launch_bounds__(256) void k_scores1(const float* __restrict__ a1) {
    int warp = threadIdx.x >> 5;
    int lane = threadIdx.x & 31;
    int n = blockIdx.x * 8 + warp;
    if (n >= N_NODES) return;
    int head = lane >> 2;
    int q = lane & 3;

    const __half* hp = g_h1h + (size_t)n * HCAT + lane * 16;
    uint4 u0 = *(const uint4*)(hp);
    uint4 u1 = *(const uint4*)(hp + 8);
    float f[16];
    {
        const __half2* c0 = (const __half2*)&u0;
        const __half2* c1 = (const __half2*)&u1;
#pragma unroll
        for (int j = 0; j < 4; ++j) {
            float2 p = __half22float2(c0[j]);
            f[2 * j] = p.x; f[2 * j + 1] = p.y;
            float2 r = __half22float2(c1[j]);
            f[8 + 2 * j] = r.x; f[8 + 2 * j + 1] = r.y;
        }
    }
    const float* as = a1 + head * (2 * NHID) + q * 16;
    const float* ad = as + NHID;
    float ps = 0.f, pd = 0.f;
#pragma unroll
    for (int j = 0; j < 16; ++j) {
        ps = fmaf(f[j], __ldg(&as[j]), ps);
        pd = fmaf(f[j], __ldg(&ad[j]), pd);
    }
    ps += __shfl_xor_sync(0xFFFFFFFFu, ps, 1);
    pd += __shfl_xor_sync(0xFFFFFFFFu, pd, 1);
    ps += __shfl_xor_sync(0xFFFFFFFFu, ps, 2);
    pd += __shfl_xor_sync(0xFFFFFFFFu, pd, 2);
    if (q == 0) {
        g_s1src[n * H1 + head] = ps;
        g_s1dst[n * H1 + head] = pd;
    }
}

// ---------------------------------------------------------------------------
// Layer-1 CSR aggregation, ALL 8 HEADS fused: warp per node.
// ---------------------------------------------------------------------------
__global__ __launch_bounds__(256) void k_agg1() {
    int warp = threadIdx.x >> 5;
    int lane = threadIdx.x & 31;
    int n = blockIdx.x * 8 + warp;
    if (n >= N_NODES) return;
    int head = lane >> 2;
    int beg = g_rowptr[n], end = g_rowptr[n + 1];
    float ssrc = __ldg(&g_s1src[n * H1 + head]);

    float af[16];
#pragma unroll
    for (int j = 0; j < 16; ++j) af[j] = 0.f;
    float rs = 0.f;

    int v = 0; float sdv = 0.f;
    if (beg < end) {
        v = __ldg(&g_dst_sorted[beg]);
        sdv = __ldg(&g_s1dst[v * H1 + head]);
    }
    for (int i = beg; i < end; ++i) {
        int vn = 0; float sdn = 0.f;
        if (i + 1 < end) {
            vn = __ldg(&g_dst_sorted[i + 1]);
            sdn = __ldg(&g_s1dst[vn * H1 + head]);
        }
        float lg = ssrc + sdv;
        lg = lg > 0.f ? lg : ALPHA * lg;
        float e = __expf(-lg);
        rs += e;
        const __half* hp = g_h1h + (size_t)v * HCAT + lane * 16;
        uint4 u0 = *(const uint4*)(hp);
        uint4 u1 = *(const uint4*)(hp + 8);
        const __half2* c0 = (const __half2*)&u0;
        const __half2* c1 = (const __half2*)&u1;
#pragma unroll
        for (int j = 0; j < 4; ++j) {
            float2 p = __half22float2(c0[j]);
            af[2 * j]     = fmaf(e, p.x, af[2 * j]);
            af[2 * j + 1] = fmaf(e, p.y, af[2 * j + 1]);
            float2 r = __half22float2(c1[j]);
            af[8 + 2 * j]     = fmaf(e, r.x, af[8 + 2 * j]);
            af[8 + 2 * j + 1] = fmaf(e, r.y, af[8 + 2 * j + 1]);
        }
        v = vn; sdv = sdn;
    }

    float inv = 1.f / rs;
    __half2 oh[8];
#pragma unroll
    for (int j = 0; j < 8; ++j) {
        float o0 = af[2 * j] * inv;
        float o1 = af[2 * j + 1] * inv;
        o0 = o0 > 0.f ? o0 : expm1f(o0);
        o1 = o1 > 0.f ? o1 : expm1f(o1);
        oh[j] = __floats2half2_rn(o0, o1);
    }
    __half* op = g_hcath + (size_t)n * HCAT + lane * 16;
    *(uint4*)(op)     = *(uint4*)&oh[0];
    *(uint4*)(op + 8) = *(uint4*)&oh[4];
}

// ---------------------------------------------------------------------------
// Layer-2 scores (16-dim dots, thread per node)
// ---------------------------------------------------------------------------
__global__ void k_scores2(const float* __restrict__ a2) {
    int n = blockIdx.x * blockDim.x + threadIdx.x;
    if (n >= N_NODES) return;
    float ps = 0.f, pd = 0.f;
    const float* hp = g_h2 + (size_t)n * NCLASS;
#pragma unroll
    for (int c = 0; c < NCLASS; ++c) {
        float v = hp[c];
        ps = fmaf(v, __ldg(&a2[c]), ps);
        pd = fmaf(v, __ldg(&a2[NCLASS + c]), pd);
    }
    g_s2src[n] = ps;
    g_s2dst[n] = pd;
}

// ---------------------------------------------------------------------------
// Layer-2 CSR aggregation + elu + log_softmax, fused: warp per node.
// lane = sub*16 + cls; sub-halves process alternating edges, then combine.
// Writes final output directly.
// ---------------------------------------------------------------------------
__global__ __launch_bounds__(256) void k_agg2f(float* __restrict__ out) {
    int warp = threadIdx.x >> 5;
    int lane = threadIdx.x & 31;
    int n = blockIdx.x * 8 + warp;
    if (n >= N_NODES) return;
    int sub = lane >> 4;      // 0 or 1: which edge parity
    int cls = lane & 15;
    int beg = g_rowptr[n], end = g_rowptr[n + 1];
    float ss = __ldg(&g_s2src[n]);

    float acc = 0.f, rs = 0.f;
    for (int i = beg + sub; i < end; i += 2) {
        int v = __ldg(&g_dst_sorted[i]);
        float lg = ss + __ldg(&g_s2dst[v]);
        lg = lg > 0.f ? lg : ALPHA * lg;
        float e = __expf(-lg);
        rs += e;
        acc = fmaf(e, __ldg(&g_h2[(size_t)v * NCLASS + cls]), acc);
    }
    // combine the two edge-parity halves
    acc += __shfl_xor_sync(0xFFFFFFFFu, acc, 16);
    rs  += __shfl_xor_sync(0xFFFFFFFFu, rs, 16);

    float x = acc / rs;
    x = x > 0.f ? x : expm1f(x);

    // log_softmax across the 16 classes (both halves hold identical values)
    float m = x;
#pragma unroll
    for (int o = 1; o < 16; o <<= 1) m = fmaxf(m, __shfl_xor_sync(0xFFFFFFFFu, m, o));
    float s = __expf(x - m);
#pragma unroll
    for (int o = 1; o < 16; o <<= 1) s += __shfl_xor_sync(0xFFFFFFFFu, s, o);
    float l = m + logf(s);
    if (lane < 16) out[(size_t)n * NCLASS + cls] = x - l;
}

// ---------------------------------------------------------------------------
// Launch
// ---------------------------------------------------------------------------
extern "C" void kernel_launch(void* const* d_in, const int* in_sizes, int n_in,
                              void* d_out, int out_size) {
    const float* x  = (const float*)d_in[0];
    const int*   ei = (const int*)d_in[1];
    const float* W1 = (const float*)d_in[2];
    const float* a1 = (const float*)d_in[3];
    const float* W2 = (const float*)d_in[4];
    const float* a2 = (const float*)d_in[5];
    float* out = (float*)d_out;

    // fp16 conversions
    k_cvt_x<<<((size_t)N_NODES * NFEAT / 8 + 255) / 256, 256>>>(x);
    k_cvt_w1<<<(H1 * NHID * NFEAT + 255) / 256, 256>>>(W1);
    k_cvt_w2<<<(NCLASS * HCAT + 255) / 256, 256>>>(W2);

    // CSR build (zero degrees via memset; rank saved -> atomic-free scatter)
    void* degp = nullptr;
    cudaGetSymbolAddress(&degp, g_deg);
    cudaMemsetAsync(degp, 0, N_NODES * sizeof(int));
    k_degree<<<(N_EDGES + 255) / 256, 256>>>(ei);
    k_scan<<<1, 1024>>>();
    k_scatter<<<(N_EDGES + 255) / 256, 256>>>(ei);

    // Layer 1
    dim3 g1((N_NODES + 127) / 128, H1);
    k_gemm1<<<g1, 256>>>();
    int nwb = (N_NODES + 7) / 8;
    k_scores1<<<nwb, 256>>>(a1);
    k_agg1<<<nwb, 256>>>();

    // Layer 2
    k_gemm2<<<(N_NODES + 127) / 128, 256>>>();
    k_scores2<<<(N_NODES + 255) / 256, 256>>>(a2);
    k_agg2f<<<nwb, 256>>>(out);
}

// round 14
// speedup vs baseline: 1.8231x; 1.0236x over previous
#include <cuda_runtime.h>
#include <cuda_fp16.h>
#include <cstdint>
#include <cstddef>

// ---------------------------------------------------------------------------
// Problem constants (fixed by the dataset)
// ---------------------------------------------------------------------------
#define N_NODES 50000
#define N_EDGES 1600000
#define NFEAT   512
#define NHID    64
#define H1      8
#define NCLASS  16
#define HCAT    (H1 * NHID)   // 512
#define ALPHA   0.2f

// ---------------------------------------------------------------------------
// Scratch (device globals; no allocation allowed)
// ---------------------------------------------------------------------------
__device__ __half g_xh[(size_t)N_NODES * NFEAT];        // x in fp16
__device__ __half g_w1t[(size_t)H1 * NHID * NFEAT];     // W1^T fp16: [h][n][k]
__device__ __half g_w2t[(size_t)NCLASS * HCAT];         // W2^T fp16: [n][k]
__device__ __half g_h1h[(size_t)N_NODES * HCAT];        // layer1 feats [n][h][f] fp16
__device__ __half g_hcath[(size_t)N_NODES * HCAT];      // concat(elu(h')) fp16
__device__ float g_h2[(size_t)N_NODES * NCLASS];        // layer2 linear (fp32)
__device__ float g_s1src[N_NODES * H1];                 // [n][h] interleaved
__device__ float g_s1dst[N_NODES * H1];                 // [n][h] interleaved
__device__ float g_s2src[N_NODES];
__device__ float g_s2dst[N_NODES];
__device__ int   g_deg[N_NODES];
__device__ int   g_rowptr[N_NODES + 1];
__device__ int   g_rank[N_EDGES];
__device__ int   g_dst_sorted[N_EDGES];

// ---------------------------------------------------------------------------
// helpers
// ---------------------------------------------------------------------------
__device__ __forceinline__ uint32_t packh2(float lo, float hi) {
    __half2 h = __floats2half2_rn(lo, hi);
    return *(uint32_t*)&h;
}

__device__ __forceinline__ void mma_fp16(float4& d,
                                         uint32_t a0, uint32_t a1,
                                         uint32_t a2, uint32_t a3,
                                         uint32_t b0, uint32_t b1) {
    asm volatile(
        "mma.sync.aligned.m16n8k16.row.col.f32.f16.f16.f32 "
        "{%0,%1,%2,%3}, {%4,%5,%6,%7}, {%8,%9}, {%0,%1,%2,%3};"
        : "+f"(d.x), "+f"(d.y), "+f"(d.z), "+f"(d.w)
        : "r"(a0), "r"(a1), "r"(a2), "r"(a3), "r"(b0), "r"(b1));
}

__device__ __forceinline__ void ldsm_x4(uint32_t& r0, uint32_t& r1,
                                        uint32_t& r2, uint32_t& r3,
                                        uint32_t addr) {
    asm volatile("ldmatrix.sync.aligned.m8n8.x4.shared.b16 {%0,%1,%2,%3}, [%4];"
                 : "=r"(r0), "=r"(r1), "=r"(r2), "=r"(r3) : "r"(addr));
}

// ---------------------------------------------------------------------------
// fp16 conversion kernels
// ---------------------------------------------------------------------------
__global__ void k_cvt_x(const float* __restrict__ x) {
    size_t i = ((size_t)blockIdx.x * blockDim.x + threadIdx.x) * 8;
    if (i >= (size_t)N_NODES * NFEAT) return;
    float4 a = *(const float4*)(x + i);
    float4 b = *(const float4*)(x + i + 4);
    uint4 u;
    u.x = packh2(a.x, a.y); u.y = packh2(a.z, a.w);
    u.z = packh2(b.x, b.y); u.w = packh2(b.z, b.w);
    *(uint4*)&g_xh[i] = u;
}

__global__ void k_cvt_w1(const float* __restrict__ W1) {
    int idx = blockIdx.x * blockDim.x + threadIdx.x;
    if (idx >= H1 * NHID * NFEAT) return;
    int k = idx & (NFEAT - 1);
    int n = (idx >> 9) & (NHID - 1);
    int h = idx >> 15;
    g_w1t[idx] = __float2half(W1[(size_t)h * NFEAT * NHID + (size_t)k * NHID + n]);
}

__global__ void k_cvt_w2(const float* __restrict__ W2) {
    int idx = blockIdx.x * blockDim.x + threadIdx.x;
    if (idx >= NCLASS * HCAT) return;
    int k = idx & (HCAT - 1);
    int n = idx >> 9;
    g_w2t[idx] = __float2half(W2[(size_t)k * NCLASS + n]);
}

// ---------------------------------------------------------------------------
// CSR construction (rank saved in degree pass -> atomic-free scatter)
// ---------------------------------------------------------------------------
__global__ void k_degree(const int* __restrict__ ei) {
    int e = blockIdx.x * blockDim.x + threadIdx.x;
    if (e < N_EDGES) {
        int r = atomicAdd(&g_deg[ei[e]], 1);
        g_rank[e] = r;
    }
}

__global__ __launch_bounds__(1024) void k_scan() {
    __shared__ int sums[1024];
    int tid = threadIdx.x;
    constexpr int CH = (N_NODES + 1023) / 1024;  // 49
    int start = tid * CH;
    int end = min(start + CH, N_NODES);
    int s = 0;
    for (int i = start; i < end; ++i) s += g_deg[i];
    sums[tid] = s;
    __syncthreads();
    for (int off = 1; off < 1024; off <<= 1) {
        int t = (tid >= off) ? sums[tid - off] : 0;
        __syncthreads();
        sums[tid] += t;
        __syncthreads();
    }
    int running = sums[tid] - s;
    for (int i = start; i < end; ++i) {
        g_rowptr[i] = running;
        running += g_deg[i];
    }
    if (tid == 1023) g_rowptr[N_NODES] = sums[1023];
}

__global__ void k_scatter(const int* __restrict__ ei) {
    int e = blockIdx.x * blockDim.x + threadIdx.x;
    if (e < N_EDGES) {
        int s = ei[e];
        int d = ei[N_EDGES + e];
        g_dst_sorted[g_rowptr[s] + g_rank[e]] = d;
    }
}

// ---------------------------------------------------------------------------
// Layer-1 GEMM: fp16 MMA m16n8k16 + ldmatrix fragment loads.
// Output layout: g_h1h[n][h*64 + c]  (all heads interleaved per node)
// BM=128, BN=64, BK=32, 256 threads = 8 warps (4m x 2n), warp tile 32x32.
// ---------------------------------------------------------------------------
#define G1_STR 40

__global__ __launch_bounds__(256) void k_gemm1() {
    constexpr int BM = 128, BN = 64, BK = 32, K = NFEAT;
    __shared__ __half As[BM * G1_STR];
    __shared__ __half Bs[BN * G1_STR];

    int h = blockIdx.y;
    const __half* A = g_xh;
    const __half* B = g_w1t + (size_t)h * NHID * NFEAT;

    int m0 = blockIdx.x * BM;
    int tid = threadIdx.x;
    int warp = tid >> 5;
    int lane = tid & 31;
    int g = lane >> 2;
    int t = lane & 3;
    int wm = warp >> 1;       // 0..3
    int wn = warp & 1;        // 0..1

    int aRow = tid >> 1;                // 0..127
    int aCol = (tid & 1) * 16;          // 0 or 16
    int bRow = tid >> 2;                // 0..63
    int bCol = (tid & 3) * 8;           // 0,8,16,24
    const bool aValid = (m0 + aRow) < N_NODES;
    const __half* Aptr = A + (size_t)(m0 + aRow) * K + aCol;
    const __half* Bptr = B + (size_t)bRow * K + bCol;

    // ldmatrix lane-address components (half-element offsets into As/Bs)
    uint32_t as_base = (uint32_t)__cvta_generic_to_shared(As);
    uint32_t bs_base = (uint32_t)__cvta_generic_to_shared(Bs);
    int a_mrow_l = wm * 32 + ((lane >> 3) & 1) * 8 + (lane & 7); // + mi*16
    int a_koff_l = (lane >> 4) * 8;                              // + kk
    int b_nrow_l = wn * 32 + ((lane >> 4) & 1) * 8 + (lane & 7); // + pair*16
    int b_koff_l = ((lane >> 3) & 1) * 8;                        // + kk

    float4 acc[2][4];
#pragma unroll
    for (int mi = 0; mi < 2; ++mi)
#pragma unroll
        for (int nj = 0; nj < 4; ++nj)
            acc[mi][nj] = make_float4(0.f, 0.f, 0.f, 0.f);

    uint4 ra0, ra1, rb;
    ra0 = aValid ? *(const uint4*)(Aptr) : make_uint4(0, 0, 0, 0);
    ra1 = aValid ? *(const uint4*)(Aptr + 8) : make_uint4(0, 0, 0, 0);
    rb  = *(const uint4*)(Bptr);

    for (int k0 = 0; k0 < K; k0 += BK) {
        __syncthreads();
        *(uint4*)&As[aRow * G1_STR + aCol]     = ra0;
        *(uint4*)&As[aRow * G1_STR + aCol + 8] = ra1;
        *(uint4*)&Bs[bRow * G1_STR + bCol]     = rb;
        __syncthreads();
        if (k0 + BK < K) {
            ra0 = aValid ? *(const uint4*)(Aptr + k0 + BK) : make_uint4(0, 0, 0, 0);
            ra1 = aValid ? *(const uint4*)(Aptr + k0 + BK + 8) : make_uint4(0, 0, 0, 0);
            rb  = *(const uint4*)(Bptr + k0 + BK);
        }
#pragma unroll
        for (int kk = 0; kk < BK; kk += 16) {
            uint32_t af[2][4];
#pragma unroll
            for (int mi = 0; mi < 2; ++mi) {
                uint32_t addr = as_base +
                    (uint32_t)(((a_mrow_l + mi * 16) * G1_STR + kk + a_koff_l) * 2);
                ldsm_x4(af[mi][0], af[mi][1], af[mi][2], af[mi][3], addr);
            }
            uint32_t bf[4][2];
#pragma unroll
            for (int p = 0; p < 2; ++p) {
                uint32_t addr = bs_base +
                    (uint32_t)(((b_nrow_l + p * 16) * G1_STR + kk + b_koff_l) * 2);
                ldsm_x4(bf[2 * p][0], bf[2 * p][1], bf[2 * p + 1][0], bf[2 * p + 1][1], addr);
            }
#pragma unroll
            for (int mi = 0; mi < 2; ++mi)
#pragma unroll
                for (int nj = 0; nj < 4; ++nj)
                    mma_fp16(acc[mi][nj],
                             af[mi][0], af[mi][1], af[mi][2], af[mi][3],
                             bf[nj][0], bf[nj][1]);
        }
    }

    // Epilogue -> interleaved layout [n][h*64 + c]
#pragma unroll
    for (int mi = 0; mi < 2; ++mi) {
#pragma unroll
        for (int nj = 0; nj < 4; ++nj) {
            int r = m0 + wm * 32 + mi * 16 + g;
            int c = h * NHID + wn * 32 + nj * 8 + t * 2;
            float4 v = acc[mi][nj];
            if (r < N_NODES) {
                uint32_t p = packh2(v.x, v.y);
                *(uint32_t*)&g_h1h[(size_t)r * HCAT + c] = p;
            }
            if (r + 8 < N_NODES) {
                uint32_t p = packh2(v.z, v.w);
                *(uint32_t*)&g_h1h[(size_t)(r + 8) * HCAT + c] = p;
            }
        }
    }
}

// ---------------------------------------------------------------------------
// Layer-2 GEMM: fp16 MMA + ldmatrix, BN=16.
// ---------------------------------------------------------------------------
__global__ __launch_bounds__(256) void k_gemm2() {
    constexpr int BM = 128, BK = 32, K = HCAT;
    __shared__ __half As[BM * G1_STR];
    __shared__ __half Bs[NCLASS * G1_STR];

    int m0 = blockIdx.x * BM;
    int tid = threadIdx.x;
    int warp = tid >> 5;
    int lane = tid & 31;
    int g = lane >> 2;
    int t = lane & 3;

    int aRow = tid >> 1;
    int aCol = (tid & 1) * 16;
    const bool aValid = (m0 + aRow) < N_NODES;
    const __half* Aptr = g_hcath + (size_t)(m0 + aRow) * K + aCol;
    int bRow = tid >> 2;            // 0..63, valid < 16
    int bCol = (tid & 3) * 8;
    const bool bAct = bRow < NCLASS;
    const __half* Bptr = g_w2t + (size_t)bRow * K + bCol;

    uint32_t as_base = (uint32_t)__cvta_generic_to_shared(As);
    uint32_t bs_base = (uint32_t)__cvta_generic_to_shared(Bs);
    int a_mrow_l = warp * 16 + ((lane >> 3) & 1) * 8 + (lane & 7);
    int a_koff_l = (lane >> 4) * 8;
    int b_nrow_l = ((lane >> 4) & 1) * 8 + (lane & 7);
    int b_koff_l = ((lane >> 3) & 1) * 8;

    float4 acc[2];
    acc[0] = make_float4(0.f, 0.f, 0.f, 0.f);
    acc[1] = make_float4(0.f, 0.f, 0.f, 0.f);

    uint4 ra0, ra1, rb;
    ra0 = aValid ? *(const uint4*)(Aptr) : make_uint4(0, 0, 0, 0);
    ra1 = aValid ? *(const uint4*)(Aptr + 8) : make_uint4(0, 0, 0, 0);
    rb  = bAct ? *(const uint4*)(Bptr) : make_uint4(0, 0, 0, 0);

    for (int k0 = 0; k0 < K; k0 += BK) {
        __syncthreads();
        *(uint4*)&As[aRow * G1_STR + aCol]     = ra0;
        *(uint4*)&As[aRow * G1_STR + aCol + 8] = ra1;
        if (bAct) *(uint4*)&Bs[bRow * G1_STR + bCol] = rb;
        __syncthreads();
        if (k0 + BK < K) {
            ra0 = aValid ? *(const uint4*)(Aptr + k0 + BK) : make_uint4(0, 0, 0, 0);
            ra1 = aValid ? *(const uint4*)(Aptr + k0 + BK + 8) : make_uint4(0, 0, 0, 0);
            rb  = bAct ? *(const uint4*)(Bptr + k0 + BK) : make_uint4(0, 0, 0, 0);
        }
#pragma unroll
        for (int kk = 0; kk < BK; kk += 16) {
            uint32_t a0, a1, a2, a3;
            {
                uint32_t addr = as_base +
                    (uint32_t)(((a_mrow_l) * G1_STR + kk + a_koff_l) * 2);
                ldsm_x4(a0, a1, a2, a3, addr);
            }
            uint32_t b00, b01, b10, b11;
            {
                uint32_t addr = bs_base +
                    (uint32_t)(((b_nrow_l) * G1_STR + kk + b_koff_l) * 2);
                ldsm_x4(b00, b01, b10, b11, addr);
            }
            mma_fp16(acc[0], a0, a1, a2, a3, b00, b01);
            mma_fp16(acc[1], a0, a1, a2, a3, b10, b11);
        }
    }

#pragma unroll
    for (int nj = 0; nj < 2; ++nj) {
        int r = m0 + warp * 16 + g;
        int c = nj * 8 + t * 2;
        float4 v = acc[nj];
        if (r < N_NODES)
            *(float2*)&g_h2[(size_t)r * NCLASS + c] = make_float2(v.x, v.y);
        if (r + 8 < N_NODES)
            *(float2*)&g_h2[(size_t)(r + 8) * NCLASS + c] = make_float2(v.z, v.w);
    }
}

// ---------------------------------------------------------------------------
// Layer-1 scores, all heads fused: warp per node.
// ---------------------------------------------------------------------------
__global__ __launch_bounds__(256) void k_scores1(const float* __restrict__ a1) {
    int warp = threadIdx.x >> 5;
    int lane = threadIdx.x & 31;
    int n = blockIdx.x * 8 + warp;
    if (n >= N_NODES) return;
    int head = lane >> 2;
    int q = lane & 3;

    const __half* hp = g_h1h + (size_t)n * HCAT + lane * 16;
    uint4 u0 = *(const uint4*)(hp);
    uint4 u1 = *(const uint4*)(hp + 8);
    float f[16];
    {
        const __half2* c0 = (const __half2*)&u0;
        const __half2* c1 = (const __half2*)&u1;
#pragma unroll
        for (int j = 0; j < 4; ++j) {
            float2 p = __half22float2(c0[j]);
            f[2 * j] = p.x; f[2 * j + 1] = p.y;
            float2 r = __half22float2(c1[j]);
            f[8 + 2 * j] = r.x; f[8 + 2 * j + 1] = r.y;
        }
    }
    const float* as = a1 + head * (2 * NHID) + q * 16;
    const float* ad = as + NHID;
    float ps = 0.f, pd = 0.f;
#pragma unroll
    for (int j = 0; j < 16; ++j) {
        ps = fmaf(f[j], __ldg(&as[j]), ps);
        pd = fmaf(f[j], __ldg(&ad[j]), pd);
    }
    ps += __shfl_xor_sync(0xFFFFFFFFu, ps, 1);
    pd += __shfl_xor_sync(0xFFFFFFFFu, pd, 1);
    ps += __shfl_xor_sync(0xFFFFFFFFu, ps, 2);
    pd += __shfl_xor_sync(0xFFFFFFFFu, pd, 2);
    if (q == 0) {
        g_s1src[n * H1 + head] = ps;
        g_s1dst[n * H1 + head] = pd;
    }
}

// ---------------------------------------------------------------------------
// Layer-1 CSR aggregation, ALL 8 HEADS fused: warp per node.
// ---------------------------------------------------------------------------
__global__ __launch_bounds__(256) void k_agg1() {
    int warp = threadIdx.x >> 5;
    int lane = threadIdx.x & 31;
    int n = blockIdx.x * 8 + warp;
    if (n >= N_NODES) return;
    int head = lane >> 2;
    int beg = g_rowptr[n], end = g_rowptr[n + 1];
    float ssrc = __ldg(&g_s1src[n * H1 + head]);

    float af[16];
#pragma unroll
    for (int j = 0; j < 16; ++j) af[j] = 0.f;
    float rs = 0.f;

    int v = 0; float sdv = 0.f;
    if (beg < end) {
        v = __ldg(&g_dst_sorted[beg]);
        sdv = __ldg(&g_s1dst[v * H1 + head]);
    }
    for (int i = beg; i < end; ++i) {
        int vn = 0; float sdn = 0.f;
        if (i + 1 < end) {
            vn = __ldg(&g_dst_sorted[i + 1]);
            sdn = __ldg(&g_s1dst[vn * H1 + head]);
        }
        float lg = ssrc + sdv;
        lg = lg > 0.f ? lg : ALPHA * lg;
        float e = __expf(-lg);
        rs += e;
        const __half* hp = g_h1h + (size_t)v * HCAT + lane * 16;
        uint4 u0 = *(const uint4*)(hp);
        uint4 u1 = *(const uint4*)(hp + 8);
        const __half2* c0 = (const __half2*)&u0;
        const __half2* c1 = (const __half2*)&u1;
#pragma unroll
        for (int j = 0; j < 4; ++j) {
            float2 p = __half22float2(c0[j]);
            af[2 * j]     = fmaf(e, p.x, af[2 * j]);
            af[2 * j + 1] = fmaf(e, p.y, af[2 * j + 1]);
            float2 r = __half22float2(c1[j]);
            af[8 + 2 * j]     = fmaf(e, r.x, af[8 + 2 * j]);
            af[8 + 2 * j + 1] = fmaf(e, r.y, af[8 + 2 * j + 1]);
        }
        v = vn; sdv = sdn;
    }

    float inv = 1.f / rs;
    __half2 oh[8];
#pragma unroll
    for (int j = 0; j < 8; ++j) {
        float o0 = af[2 * j] * inv;
        float o1 = af[2 * j + 1] * inv;
        o0 = o0 > 0.f ? o0 : expm1f(o0);
        o1 = o1 > 0.f ? o1 : expm1f(o1);
        oh[j] = __floats2half2_rn(o0, o1);
    }
    __half* op = g_hcath + (size_t)n * HCAT + lane * 16;
    *(uint4*)(op)     = *(uint4*)&oh[0];
    *(uint4*)(op + 8) = *(uint4*)&oh[4];
}

// ---------------------------------------------------------------------------
// Layer-2 scores (16-dim dots, thread per node)
// ---------------------------------------------------------------------------
__global__ void k_scores2(const float* __restrict__ a2) {
    int n = blockIdx.x * blockDim.x + threadIdx.x;
    if (n >= N_NODES) return;
    float ps = 0.f, pd = 0.f;
    const float* hp = g_h2 + (size_t)n * NCLASS;
#pragma unroll
    for (int c = 0; c < NCLASS; ++c) {
        float v = hp[c];
        ps = fmaf(v, __ldg(&a2[c]), ps);
        pd = fmaf(v, __ldg(&a2[NCLASS + c]), pd);
    }
    g_s2src[n] = ps;
    g_s2dst[n] = pd;
}

// ---------------------------------------------------------------------------
// Layer-2 CSR aggregation + elu + log_softmax, fused: warp per node.
// ---------------------------------------------------------------------------
__global__ __launch_bounds__(256) void k_agg2f(float* __restrict__ out) {
    int warp = threadIdx.x >> 5;
    int lane = threadIdx.x & 31;
    int n = blockIdx.x * 8 + warp;
    if (n >= N_NODES) return;
    int sub = lane >> 4;      // 0 or 1: which edge parity
    int cls = lane & 15;
    int beg = g_rowptr[n], end = g_rowptr[n + 1];
    float ss = __ldg(&g_s2src[n]);

    float acc = 0.f, rs = 0.f;
    for (int i = beg + sub; i < end; i += 2) {
        int v = __ldg(&g_dst_sorted[i]);
        float lg = ss + __ldg(&g_s2dst[v]);
        lg = lg > 0.f ? lg : ALPHA * lg;
        float e = __expf(-lg);
        rs += e;
        acc = fmaf(e, __ldg(&g_h2[(size_t)v * NCLASS + cls]), acc);
    }
    acc += __shfl_xor_sync(0xFFFFFFFFu, acc, 16);
    rs  += __shfl_xor_sync(0xFFFFFFFFu, rs, 16);

    float x = acc / rs;
    x = x > 0.f ? x : expm1f(x);

    float m = x;
#pragma unroll
    for (int o = 1; o < 16; o <<= 1) m = fmaxf(m, __shfl_xor_sync(0xFFFFFFFFu, m, o));
    float s = __expf(x - m);
#pragma unroll
    for (int o = 1; o < 16; o <<= 1) s += __shfl_xor_sync(0xFFFFFFFFu, s, o);
    float l = m + logf(s);
    if (lane < 16) out[(size_t)n * NCLASS + cls] = x - l;
}

// ---------------------------------------------------------------------------
// Launch
// ---------------------------------------------------------------------------
extern "C" void kernel_launch(void* const* d_in, const int* in_sizes, int n_in,
                              void* d_out, int out_size) {
    const float* x  = (const float*)d_in[0];
    const int*   ei = (const int*)d_in[1];
    const float* W1 = (const float*)d_in[2];
    const float* a1 = (const float*)d_in[3];
    const float* W2 = (const float*)d_in[4];
    const float* a2 = (const float*)d_in[5];
    float* out = (float*)d_out;

    // fp16 conversions
    k_cvt_x<<<((size_t)N_NODES * NFEAT / 8 + 255) / 256, 256>>>(x);
    k_cvt_w1<<<(H1 * NHID * NFEAT + 255) / 256, 256>>>(W1);
    k_cvt_w2<<<(NCLASS * HCAT + 255) / 256, 256>>>(W2);

    // CSR build
    void* degp = nullptr;
    cudaGetSymbolAddress(&degp, g_deg);
    cudaMemsetAsync(degp, 0, N_NODES * sizeof(int));
    k_degree<<<(N_EDGES + 255) / 256, 256>>>(ei);
    k_scan<<<1, 1024>>>();
    k_scatter<<<(N_EDGES + 255) / 256, 256>>>(ei);

    // Layer 1
    dim3 g1((N_NODES + 127) / 128, H1);
    k_gemm1<<<g1, 256>>>();
    int nwb = (N_NODES + 7) / 8;
    k_scores1<<<nwb, 256>>>(a1);
    k_agg1<<<nwb, 256>>>();

    // Layer 2
    k_gemm2<<<(N_NODES + 127) / 128, 256>>>();
    k_scores2<<<(N_NODES + 255) / 256, 256>>>(a2);
    k_agg2f<<<nwb, 256>>>(out);
}

// round 15
// speedup vs baseline: 2.0145x; 1.1050x over previous
#include <cuda_runtime.h>
#include <cuda_fp16.h>
#include <cstdint>
#include <cstddef>

// ---------------------------------------------------------------------------
// Problem constants (fixed by the dataset)
// ---------------------------------------------------------------------------
#define N_NODES 50000
#define N_EDGES 1600000
#define NFEAT   512
#define NHID    64
#define H1      8
#define NCLASS  16
#define HCAT    (H1 * NHID)   // 512
#define ALPHA   0.2f

// ---------------------------------------------------------------------------
// Scratch (device globals; no allocation allowed)
// ---------------------------------------------------------------------------
__device__ __half g_xh[(size_t)N_NODES * NFEAT];        // x in fp16
__device__ __half g_w1t[(size_t)H1 * NHID * NFEAT];     // W1^T fp16: [h][n][k]
__device__ __half g_w2t[(size_t)NCLASS * HCAT];         // W2^T fp16: [n][k]
__device__ __half g_h1h[(size_t)N_NODES * HCAT];        // layer1 feats [n][h][f] fp16
__device__ __half g_hcath[(size_t)N_NODES * HCAT];      // concat(elu(h')) fp16
__device__ float g_h2[(size_t)N_NODES * NCLASS];        // layer2 linear (fp32)
__device__ float g_s1src[N_NODES * H1];                 // [n][h] interleaved
__device__ float g_s1dst[N_NODES * H1];                 // [n][h] interleaved
__device__ float g_s2src[N_NODES];
__device__ float g_s2dst[N_NODES];
__device__ int   g_deg[N_NODES];
__device__ int   g_rowptr[N_NODES + 1];
__device__ int   g_rank[N_EDGES];
__device__ int   g_dst_sorted[N_EDGES];

// ---------------------------------------------------------------------------
// helpers
// ---------------------------------------------------------------------------
__device__ __forceinline__ uint32_t packh2(float lo, float hi) {
    __half2 h = __floats2half2_rn(lo, hi);
    return *(uint32_t*)&h;
}

__device__ __forceinline__ void mma_fp16(float4& d,
                                         uint32_t a0, uint32_t a1,
                                         uint32_t a2, uint32_t a3,
                                         uint32_t b0, uint32_t b1) {
    asm volatile(
        "mma.sync.aligned.m16n8k16.row.col.f32.f16.f16.f32 "
        "{%0,%1,%2,%3}, {%4,%5,%6,%7}, {%8,%9}, {%0,%1,%2,%3};"
        : "+f"(d.x), "+f"(d.y), "+f"(d.z), "+f"(d.w)
        : "r"(a0), "r"(a1), "r"(a2), "r"(a3), "r"(b0), "r"(b1));
}

__device__ __forceinline__ void ldsm_x4(uint32_t& r0, uint32_t& r1,
                                        uint32_t& r2, uint32_t& r3,
                                        uint32_t addr) {
    asm volatile("ldmatrix.sync.aligned.m8n8.x4.shared.b16 {%0,%1,%2,%3}, [%4];"
                 : "=r"(r0), "=r"(r1), "=r"(r2), "=r"(r3) : "r"(addr));
}

// ---------------------------------------------------------------------------
// fp16 conversion kernels
// ---------------------------------------------------------------------------
__global__ void k_cvt_x(const float* __restrict__ x) {
    size_t i = ((size_t)blockIdx.x * blockDim.x + threadIdx.x) * 8;
    if (i >= (size_t)N_NODES * NFEAT) return;
    float4 a = *(const float4*)(x + i);
    float4 b = *(const float4*)(x + i + 4);
    uint4 u;
    u.x = packh2(a.x, a.y); u.y = packh2(a.z, a.w);
    u.z = packh2(b.x, b.y); u.w = packh2(b.z, b.w);
    *(uint4*)&g_xh[i] = u;
}

__global__ void k_cvt_w1(const float* __restrict__ W1) {
    int idx = blockIdx.x * blockDim.x + threadIdx.x;
    if (idx >= H1 * NHID * NFEAT) return;
    int k = idx & (NFEAT - 1);
    int n = (idx >> 9) & (NHID - 1);
    int h = idx >> 15;
    g_w1t[idx] = __float2half(W1[(size_t)h * NFEAT * NHID + (size_t)k * NHID + n]);
}

__global__ void k_cvt_w2(const float* __restrict__ W2) {
    int idx = blockIdx.x * blockDim.x + threadIdx.x;
    if (idx >= NCLASS * HCAT) return;
    int k = idx & (HCAT - 1);
    int n = idx >> 9;
    g_w2t[idx] = __float2half(W2[(size_t)k * NCLASS + n]);
}

// ---------------------------------------------------------------------------
// CSR construction (rank saved in degree pass -> atomic-free scatter)
// ---------------------------------------------------------------------------
__global__ void k_degree(const int* __restrict__ ei) {
    int e = blockIdx.x * blockDim.x + threadIdx.x;
    if (e < N_EDGES) {
        int r = atomicAdd(&g_deg[ei[e]], 1);
        g_rank[e] = r;
    }
}

__global__ __launch_bounds__(1024) void k_scan() {
    __shared__ int sums[1024];
    int tid = threadIdx.x;
    constexpr int CH = (N_NODES + 1023) / 1024;  // 49
    int start = tid * CH;
    int end = min(start + CH, N_NODES);
    int s = 0;
    for (int i = start; i < end; ++i) s += g_deg[i];
    sums[tid] = s;
    __syncthreads();
    for (int off = 1; off < 1024; off <<= 1) {
        int t = (tid >= off) ? sums[tid - off] : 0;
        __syncthreads();
        sums[tid] += t;
        __syncthreads();
    }
    int running = sums[tid] - s;
    for (int i = start; i < end; ++i) {
        g_rowptr[i] = running;
        running += g_deg[i];
    }
    if (tid == 1023) g_rowptr[N_NODES] = sums[1023];
}

__global__ void k_scatter(const int* __restrict__ ei) {
    int e = blockIdx.x * blockDim.x + threadIdx.x;
    if (e < N_EDGES) {
        int s = ei[e];
        int d = ei[N_EDGES + e];
        g_dst_sorted[g_rowptr[s] + g_rank[e]] = d;
    }
}

// ---------------------------------------------------------------------------
// Layer-1 GEMM: fp16 MMA m16n8k16 + ldmatrix fragment loads.
// Output layout: g_h1h[n][h*64 + c]  (all heads interleaved per node)
// BM=128, BN=64, BK=32, 256 threads = 8 warps (4m x 2n), warp tile 32x32.
// ---------------------------------------------------------------------------
#define G1_STR 40

__global__ __launch_bounds__(256) void k_gemm1() {
    constexpr int BM = 128, BN = 64, BK = 32, K = NFEAT;
    __shared__ __half As[BM * G1_STR];
    __shared__ __half Bs[BN * G1_STR];

    int h = blockIdx.y;
    const __half* A = g_xh;
    const __half* B = g_w1t + (size_t)h * NHID * NFEAT;

    int m0 = blockIdx.x * BM;
    int tid = threadIdx.x;
    int warp = tid >> 5;
    int lane = tid & 31;
    int g = lane >> 2;
    int t = lane & 3;
    int wm = warp >> 1;       // 0..3
    int wn = warp & 1;        // 0..1

    int aRow = tid >> 1;                // 0..127
    int aCol = (tid & 1) * 16;          // 0 or 16
    int bRow = tid >> 2;                // 0..63
    int bCol = (tid & 3) * 8;           // 0,8,16,24
    const bool aValid = (m0 + aRow) < N_NODES;
    const __half* Aptr = A + (size_t)(m0 + aRow) * K + aCol;
    const __half* Bptr = B + (size_t)bRow * K + bCol;

    uint32_t as_base = (uint32_t)__cvta_generic_to_shared(As);
    uint32_t bs_base = (uint32_t)__cvta_generic_to_shared(Bs);
    int a_mrow_l = wm * 32 + ((lane >> 3) & 1) * 8 + (lane & 7); // + mi*16
    int a_koff_l = (lane >> 4) * 8;                              // + kk
    int b_nrow_l = wn * 32 + ((lane >> 4) & 1) * 8 + (lane & 7); // + pair*16
    int b_koff_l = ((lane >> 3) & 1) * 8;                        // + kk

    float4 acc[2][4];
#pragma unroll
    for (int mi = 0; mi < 2; ++mi)
#pragma unroll
        for (int nj = 0; nj < 4; ++nj)
            acc[mi][nj] = make_float4(0.f, 0.f, 0.f, 0.f);

    uint4 ra0, ra1, rb;
    ra0 = aValid ? *(const uint4*)(Aptr) : make_uint4(0, 0, 0, 0);
    ra1 = aValid ? *(const uint4*)(Aptr + 8) : make_uint4(0, 0, 0, 0);
    rb  = *(const uint4*)(Bptr);

    for (int k0 = 0; k0 < K; k0 += BK) {
        __syncthreads();
        *(uint4*)&As[aRow * G1_STR + aCol]     = ra0;
        *(uint4*)&As[aRow * G1_STR + aCol + 8] = ra1;
        *(uint4*)&Bs[bRow * G1_STR + bCol]     = rb;
        __syncthreads();
        if (k0 + BK < K) {
            ra0 = aValid ? *(const uint4*)(Aptr + k0 + BK) : make_uint4(0, 0, 0, 0);
            ra1 = aValid ? *(const uint4*)(Aptr + k0 + BK + 8) : make_uint4(0, 0, 0, 0);
            rb  = *(const uint4*)(Bptr + k0 + BK);
        }
#pragma unroll
        for (int kk = 0; kk < BK; kk += 16) {
            uint32_t af[2][4];
#pragma unroll
            for (int mi = 0; mi < 2; ++mi) {
                uint32_t addr = as_base +
                    (uint32_t)(((a_mrow_l + mi * 16) * G1_STR + kk + a_koff_l) * 2);
                ldsm_x4(af[mi][0], af[mi][1], af[mi][2], af[mi][3], addr);
            }
            uint32_t bf[4][2];
#pragma unroll
            for (int p = 0; p < 2; ++p) {
                uint32_t addr = bs_base +
                    (uint32_t)(((b_nrow_l + p * 16) * G1_STR + kk + b_koff_l) * 2);
                ldsm_x4(bf[2 * p][0], bf[2 * p][1], bf[2 * p + 1][0], bf[2 * p + 1][1], addr);
            }
#pragma unroll
            for (int mi = 0; mi < 2; ++mi)
#pragma unroll
                for (int nj = 0; nj < 4; ++nj)
                    mma_fp16(acc[mi][nj],
                             af[mi][0], af[mi][1], af[mi][2], af[mi][3],
                             bf[nj][0], bf[nj][1]);
        }
    }

    // Epilogue -> interleaved layout [n][h*64 + c]
#pragma unroll
    for (int mi = 0; mi < 2; ++mi) {
#pragma unroll
        for (int nj = 0; nj < 4; ++nj) {
            int r = m0 + wm * 32 + mi * 16 + g;
            int c = h * NHID + wn * 32 + nj * 8 + t * 2;
            float4 v = acc[mi][nj];
            if (r < N_NODES) {
                uint32_t p = packh2(v.x, v.y);
                *(uint32_t*)&g_h1h[(size_t)r * HCAT + c] = p;
            }
            if (r + 8 < N_NODES) {
                uint32_t p = packh2(v.z, v.w);
                *(uint32_t*)&g_h1h[(size_t)(r + 8) * HCAT + c] = p;
            }
        }
    }
}

// ---------------------------------------------------------------------------
// Layer-2 GEMM: fp16 MMA + ldmatrix, BN=16.
// ---------------------------------------------------------------------------
__global__ __launch_bounds__(256) void k_gemm2() {
    constexpr int BM = 128, BK = 32, K = HCAT;
    __shared__ __half As[BM * G1_STR];
    __shared__ __half Bs[NCLASS * G1_STR];

    int m0 = blockIdx.x * BM;
    int tid = threadIdx.x;
    int warp = tid >> 5;
    int lane = tid & 31;
    int g = lane >> 2;
    int t = lane & 3;

    int aRow = tid >> 1;
    int aCol = (tid & 1) * 16;
    const bool aValid = (m0 + aRow) < N_NODES;
    const __half* Aptr = g_hcath + (size_t)(m0 + aRow) * K + aCol;
    int bRow = tid >> 2;            // 0..63, valid < 16
    int bCol = (tid & 3) * 8;
    const bool bAct = bRow < NCLASS;
    const __half* Bptr = g_w2t + (size_t)bRow * K + bCol;

    uint32_t as_base = (uint32_t)__cvta_generic_to_shared(As);
    uint32_t bs_base = (uint32_t)__cvta_generic_to_shared(Bs);
    int a_mrow_l = warp * 16 + ((lane >> 3) & 1) * 8 + (lane & 7);
    int a_koff_l = (lane >> 4) * 8;
    int b_nrow_l = ((lane >> 4) & 1) * 8 + (lane & 7);
    int b_koff_l = ((lane >> 3) & 1) * 8;

    float4 acc[2];
    acc[0] = make_float4(0.f, 0.f, 0.f, 0.f);
    acc[1] = make_float4(0.f, 0.f, 0.f, 0.f);

    uint4 ra0, ra1, rb;
    ra0 = aValid ? *(const uint4*)(Aptr) : make_uint4(0, 0, 0, 0);
    ra1 = aValid ? *(const uint4*)(Aptr + 8) : make_uint4(0, 0, 0, 0);
    rb  = bAct ? *(const uint4*)(Bptr) : make_uint4(0, 0, 0, 0);

    for (int k0 = 0; k0 < K; k0 += BK) {
        __syncthreads();
        *(uint4*)&As[aRow * G1_STR + aCol]     = ra0;
        *(uint4*)&As[aRow * G1_STR + aCol + 8] = ra1;
        if (bAct) *(uint4*)&Bs[bRow * G1_STR + bCol] = rb;
        __syncthreads();
        if (k0 + BK < K) {
            ra0 = aValid ? *(const uint4*)(Aptr + k0 + BK) : make_uint4(0, 0, 0, 0);
            ra1 = aValid ? *(const uint4*)(Aptr + k0 + BK + 8) : make_uint4(0, 0, 0, 0);
            rb  = bAct ? *(const uint4*)(Bptr + k0 + BK) : make_uint4(0, 0, 0, 0);
        }
#pragma unroll
        for (int kk = 0; kk < BK; kk += 16) {
            uint32_t a0, a1, a2, a3;
            {
                uint32_t addr = as_base +
                    (uint32_t)(((a_mrow_l) * G1_STR + kk + a_koff_l) * 2);
                ldsm_x4(a0, a1, a2, a3, addr);
            }
            uint32_t b00, b01, b10, b11;
            {
                uint32_t addr = bs_base +
                    (uint32_t)(((b_nrow_l) * G1_STR + kk + b_koff_l) * 2);
                ldsm_x4(b00, b01, b10, b11, addr);
            }
            mma_fp16(acc[0], a0, a1, a2, a3, b00, b01);
            mma_fp16(acc[1], a0, a1, a2, a3, b10, b11);
        }
    }

#pragma unroll
    for (int nj = 0; nj < 2; ++nj) {
        int r = m0 + warp * 16 + g;
        int c = nj * 8 + t * 2;
        float4 v = acc[nj];
        if (r < N_NODES)
            *(float2*)&g_h2[(size_t)r * NCLASS + c] = make_float2(v.x, v.y);
        if (r + 8 < N_NODES)
            *(float2*)&g_h2[(size_t)(r + 8) * NCLASS + c] = make_float2(v.z, v.w);
    }
}

// ---------------------------------------------------------------------------
// Layer-1 scores, all heads fused: warp per node.
// ---------------------------------------------------------------------------
__global__ __launch_bounds__(256) void k_scores1(const float* __restrict__ a1) {
    int warp = threadIdx.x >> 5;
    int lane = threadIdx.x & 31;
    int n = blockIdx.x * 8 + warp;
    if (n >= N_NODES) return;
    int head = lane >> 2;
    int q = lane & 3;

    const __half* hp = g_h1h + (size_t)n * HCAT + lane * 16;
    uint4 u0 = *(const uint4*)(hp);
    uint4 u1 = *(const uint4*)(hp + 8);
    float f[16];
    {
        const __half2* c0 = (const __half2*)&u0;
        const __half2* c1 = (const __half2*)&u1;
#pragma unroll
        for (int j = 0; j < 4; ++j) {
            float2 p = __half22float2(c0[j]);
            f[2 * j] = p.x; f[2 * j + 1] = p.y;
            float2 r = __half22float2(c1[j]);
            f[8 + 2 * j] = r.x; f[8 + 2 * j + 1] = r.y;
        }
    }
    const float* as = a1 + head * (2 * NHID) + q * 16;
    const float* ad = as + NHID;
    float ps = 0.f, pd = 0.f;
#pragma unroll
    for (int j = 0; j < 16; ++j) {
        ps = fmaf(f[j], __ldg(&as[j]), ps);
        pd = fmaf(f[j], __ldg(&ad[j]), pd);
    }
    ps += __shfl_xor_sync(0xFFFFFFFFu, ps, 1);
    pd += __shfl_xor_sync(0xFFFFFFFFu, pd, 1);
    ps += __shfl_xor_sync(0xFFFFFFFFu, ps, 2);
    pd += __shfl_xor_sync(0xFFFFFFFFu, pd, 2);
    if (q == 0) {
        g_s1src[n * H1 + head] = ps;
        g_s1dst[n * H1 + head] = pd;
    }
}

// ---------------------------------------------------------------------------
// Layer-1 CSR aggregation, ALL 8 HEADS fused: warp per node.
// ---------------------------------------------------------------------------
__global__ __launch_bounds__(256) void k_agg1() {
    int warp = threadIdx.x >> 5;
    int lane = threadIdx.x & 31;
    int n = blockIdx.x * 8 + warp;
    if (n >= N_NODES) return;
    int head = lane >> 2;
    int beg = g_rowptr[n], end = g_rowptr[n + 1];
    float ssrc = __ldg(&g_s1src[n * H1 + head]);

    float af[16];
#pragma unroll
    for (int j = 0; j < 16; ++j) af[j] = 0.f;
    float rs = 0.f;

    int v = 0; float sdv = 0.f;
    if (beg < end) {
        v = __ldg(&g_dst_sorted[beg]);
        sdv = __ldg(&g_s1dst[v * H1 + head]);
    }
    for (int i = beg; i < end; ++i) {
        int vn = 0; float sdn = 0.f;
        if (i + 1 < end) {
            vn = __ldg(&g_dst_sorted[i + 1]);
            sdn = __ldg(&g_s1dst[vn * H1 + head]);
        }
        float lg = ssrc + sdv;
        lg = lg > 0.f ? lg : ALPHA * lg;
        float e = __expf(-lg);
        rs += e;
        const __half* hp = g_h1h + (size_t)v * HCAT + lane * 16;
        uint4 u0 = *(const uint4*)(hp);
        uint4 u1 = *(const uint4*)(hp + 8);
        const __half2* c0 = (const __half2*)&u0;
        const __half2* c1 = (const __half2*)&u1;
#pragma unroll
        for (int j = 0; j < 4; ++j) {
            float2 p = __half22float2(c0[j]);
            af[2 * j]     = fmaf(e, p.x, af[2 * j]);
            af[2 * j + 1] = fmaf(e, p.y, af[2 * j + 1]);
            float2 r = __half22float2(c1[j]);
            af[8 + 2 * j]     = fmaf(e, r.x, af[8 + 2 * j]);
            af[8 + 2 * j + 1] = fmaf(e, r.y, af[8 + 2 * j + 1]);
        }
        v = vn; sdv = sdn;
    }

    float inv = 1.f / rs;
    __half2 oh[8];
#pragma unroll
    for (int j = 0; j < 8; ++j) {
        float o0 = af[2 * j] * inv;
        float o1 = af[2 * j + 1] * inv;
        o0 = o0 > 0.f ? o0 : expm1f(o0);
        o1 = o1 > 0.f ? o1 : expm1f(o1);
        oh[j] = __floats2half2_rn(o0, o1);
    }
    __half* op = g_hcath + (size_t)n * HCAT + lane * 16;
    *(uint4*)(op)     = *(uint4*)&oh[0];
    *(uint4*)(op + 8) = *(uint4*)&oh[4];
}

// ---------------------------------------------------------------------------
// Layer-2 scores (16-dim dots, thread per node)
// ---------------------------------------------------------------------------
__global__ void k_scores2(const float* __restrict__ a2) {
    int n = blockIdx.x * blockDim.x + threadIdx.x;
    if (n >= N_NODES) return;
    float ps = 0.f, pd = 0.f;
    const float* hp = g_h2 + (size_t)n * NCLASS;
#pragma unroll
    for (int c = 0; c < NCLASS; ++c) {
        float v = hp[c];
        ps = fmaf(v, __ldg(&a2[c]), ps);
        pd = fmaf(v, __ldg(&a2[NCLASS + c]), pd);
    }
    g_s2src[n] = ps;
    g_s2dst[n] = pd;
}

// ---------------------------------------------------------------------------
// Layer-2 CSR aggregation + elu + log_softmax, fused: warp per node.
// ---------------------------------------------------------------------------
__global__ __launch_bounds__(256) void k_agg2f(float* __restrict__ out) {
    int warp = threadIdx.x >> 5;
    int lane = threadIdx.x & 31;
    int n = blockIdx.x * 8 + warp;
    if (n >= N_NODES) return;
    int sub = lane >> 4;      // 0 or 1: which edge parity
    int cls = lane & 15;
    int beg = g_rowptr[n], end = g_rowptr[n + 1];
    float ss = __ldg(&g_s2src[n]);

    float acc = 0.f, rs = 0.f;
    for (int i = beg + sub; i < end; i += 2) {
        int v = __ldg(&g_dst_sorted[i]);
        float lg = ss + __ldg(&g_s2dst[v]);
        lg = lg > 0.f ? lg : ALPHA * lg;
        float e = __expf(-lg);
        rs += e;
        acc = fmaf(e, __ldg(&g_h2[(size_t)v * NCLASS + cls]), acc);
    }
    acc += __shfl_xor_sync(0xFFFFFFFFu, acc, 16);
    rs  += __shfl_xor_sync(0xFFFFFFFFu, rs, 16);

    float x = acc / rs;
    x = x > 0.f ? x : expm1f(x);

    float m = x;
#pragma unroll
    for (int o = 1; o < 16; o <<= 1) m = fmaxf(m, __shfl_xor_sync(0xFFFFFFFFu, m, o));
    float s = __expf(x - m);
#pragma unroll
    for (int o = 1; o < 16; o <<= 1) s += __shfl_xor_sync(0xFFFFFFFFu, s, o);
    float l = m + logf(s);
    if (lane < 16) out[(size_t)n * NCLASS + cls] = x - l;
}

// ---------------------------------------------------------------------------
// Launch: CSR chain forked onto a side stream, overlapping layer-1 chain.
// Streams/events created once at first (uncaptured) correctness call;
// every call performs the identical launch sequence.
// ---------------------------------------------------------------------------
extern "C" void kernel_launch(void* const* d_in, const int* in_sizes, int n_in,
                              void* d_out, int out_size) {
    const float* x  = (const float*)d_in[0];
    const int*   ei = (const int*)d_in[1];
    const float* W1 = (const float*)d_in[2];
    const float* a1 = (const float*)d_in[3];
    const float* W2 = (const float*)d_in[4];
    const float* a2 = (const float*)d_in[5];
    float* out = (float*)d_out;

    static cudaStream_t sB = [] {
        cudaStream_t s;
        cudaStreamCreateWithFlags(&s, cudaStreamNonBlocking);
        return s;
    }();
    static cudaEvent_t evFork = [] {
        cudaEvent_t e;
        cudaEventCreateWithFlags(&e, cudaEventDisableTiming);
        return e;
    }();
    static cudaEvent_t evJoin = [] {
        cudaEvent_t e;
        cudaEventCreateWithFlags(&e, cudaEventDisableTiming);
        return e;
    }();

    void* degp = nullptr;
    cudaGetSymbolAddress(&degp, g_deg);

    // Fork: CSR build on side stream (depends only on edge_index)
    cudaEventRecord(evFork, 0);
    cudaStreamWaitEvent(sB, evFork, 0);
    cudaMemsetAsync(degp, 0, N_NODES * sizeof(int), sB);
    k_degree<<<(N_EDGES + 255) / 256, 256, 0, sB>>>(ei);
    k_scan<<<1, 1024, 0, sB>>>();
    k_scatter<<<(N_EDGES + 255) / 256, 256, 0, sB>>>(ei);
    cudaEventRecord(evJoin, sB);

    // Main stream: conversions + layer-1 dense chain
    k_cvt_x<<<((size_t)N_NODES * NFEAT / 8 + 255) / 256, 256>>>(x);
    k_cvt_w1<<<(H1 * NHID * NFEAT + 255) / 256, 256>>>(W1);
    k_cvt_w2<<<(NCLASS * HCAT + 255) / 256, 256>>>(W2);
    dim3 g1((N_NODES + 127) / 128, H1);
    k_gemm1<<<g1, 256>>>();
    int nwb = (N_NODES + 7) / 8;
    k_scores1<<<nwb, 256>>>(a1);

    // Join: aggregation needs the CSR
    cudaStreamWaitEvent(0, evJoin, 0);
    k_agg1<<<nwb, 256>>>();

    // Layer 2
    k_gemm2<<<(N_NODES + 127) / 128, 256>>>();
    k_scores2<<<(N_NODES + 255) / 256, 256>>>(a2);
    k_agg2f<<<nwb, 256>>>(out);
}